// round 11
// baseline (speedup 1.0000x reference)
#include <cuda_runtime.h>
#include <cstdint>

#define BATCH 4
#define SEQ   2048
#define CH    1024
#define NHEAD 16
#define HDIM  64
#define LOG2E 1.4426950408889634f

// Scratch (allocation-free rule: __device__ globals).
// q,k: [b,h,t,d]; v: [b,h,d,t] (transposed for PV ldmatrix).
__device__ float g_q[BATCH * NHEAD * SEQ * HDIM];
__device__ float g_k[BATCH * NHEAD * SEQ * HDIM];
__device__ float g_v[BATCH * NHEAD * HDIM * SEQ];
__device__ float g_att[BATCH * SEQ * CH];        // [b,t,c], tf32-rounded
__device__ float g_x [BATCH * SEQ * CH];         // x, tf32-rounded
__device__ float g_wa[3 * CH * CH];              // w_attn^T: [3072][1024], tf32
__device__ float g_wp[CH * CH];                  // w_proj^T: [1024][1024], tf32

__device__ __forceinline__ float to_tf32(float x) {
    float r;
    asm("cvt.rna.tf32.f32 %0, %1;" : "=f"(r) : "f"(x));
    return r;
}

#define MMA_TF32(d, a, b)                                                  \
    asm volatile(                                                          \
        "mma.sync.aligned.m16n8k8.row.col.f32.tf32.tf32.f32 "              \
        "{%0,%1,%2,%3},{%4,%5,%6,%7},{%8,%9},{%0,%1,%2,%3};"               \
        : "+f"((d)[0]), "+f"((d)[1]), "+f"((d)[2]), "+f"((d)[3])           \
        : "r"((a)[0]), "r"((a)[1]), "r"((a)[2]), "r"((a)[3]),              \
          "r"((b)[0]), "r"((b)[1]))

// ldmatrix x4 on b16 8x8 tiles == 8x4 fp32 blocks (tf32 fragment layout).
#define LDM_X4(r, addr)                                                    \
    asm volatile("ldmatrix.sync.aligned.m8n8.x4.shared.b16 "               \
                 "{%0,%1,%2,%3}, [%4];"                                    \
                 : "=r"((r)[0]), "=r"((r)[1]), "=r"((r)[2]), "=r"((r)[3])  \
                 : "r"(addr))

#define CP_ASYNC16(dst_u32, src_ptr)                                       \
    asm volatile("cp.async.cg.shared.global [%0], [%1], 16;"               \
                 :: "r"(dst_u32), "l"(src_ptr))
#define CP_COMMIT() asm volatile("cp.async.commit_group;")
#define CP_WAIT(N)  asm volatile("cp.async.wait_group %0;" :: "n"(N))

// ---- mbarrier helpers ----
#define MBAR_INIT(addr, cnt)                                               \
    asm volatile("mbarrier.init.shared::cta.b64 [%0], %1;"                 \
                 :: "r"(addr), "r"((uint32_t)(cnt)) : "memory")
#define MBAR_ARRIVE(addr)                                                  \
    asm volatile("{\n\t.reg .b64 t;\n\t"                                   \
                 "mbarrier.arrive.shared::cta.b64 t, [%0];\n\t}"           \
                 :: "r"(addr) : "memory")
#define CPA_MBAR_ARRIVE(addr)                                              \
    asm volatile("cp.async.mbarrier.arrive.noinc.shared::cta.b64 [%0];"    \
                 :: "r"(addr) : "memory")

__device__ __forceinline__ void mbar_wait(uint32_t mbar, uint32_t parity) {
    asm volatile(
        "{\n\t.reg .pred P;\n\t"
        "W_%=:\n\t"
        "mbarrier.try_wait.parity.acquire.cta.shared::cta.b64 P, [%0], %1, 0x989680;\n\t"
        "@!P bra W_%=;\n\t"
        "}" :: "r"(mbar), "r"(parity) : "memory");
}

__device__ __forceinline__ uint32_t smem_u32(const void* p) {
    return (uint32_t)__cvta_generic_to_shared(p);
}

// ---------------------------------------------------------------------------
// Prologue converts
// ---------------------------------------------------------------------------
__global__ void cvt_x_kernel(const float* __restrict__ src, int n4)
{
    int i = blockIdx.x * blockDim.x + threadIdx.x;
    if (i < n4) {
        float4 v = reinterpret_cast<const float4*>(src)[i];
        v.x = to_tf32(v.x); v.y = to_tf32(v.y);
        v.z = to_tf32(v.z); v.w = to_tf32(v.w);
        reinterpret_cast<float4*>(g_x)[i] = v;
    }
}

__global__ void cvt_T_kernel(const float* __restrict__ src, int sel, int N)
{
    __shared__ float tile[32][33];
    float* dst = (sel == 1) ? g_wa : g_wp;
    int n0 = blockIdx.x * 32, k0 = blockIdx.y * 32;
    int tx = threadIdx.x, ty = threadIdx.y;  // 32 x 8
#pragma unroll
    for (int i = 0; i < 4; i++)
        tile[ty + 8 * i][tx] = src[(size_t)(k0 + ty + 8 * i) * N + n0 + tx];
    __syncthreads();
#pragma unroll
    for (int i = 0; i < 4; i++)
        dst[(size_t)(n0 + ty + 8 * i) * CH + k0 + tx] = to_tf32(tile[tx][ty + 8 * i]);
}

// ---------------------------------------------------------------------------
// TF32 GEMM core (round-9/10 best): 128x128 block, BK=32, 8 warps (2x4),
// 3-stage cp.async pipeline + register double-buffered A fragments.
// ---------------------------------------------------------------------------
#define GS 36
#define GBUF (128 * GS)
#define NSTAGE 3
#define GEMM_SMEM (2 * NSTAGE * GBUF * (int)sizeof(float))   // 110592 B
#define EPS 132    // epilogue staging stride (floats)

__device__ __forceinline__ void gemm_issue_loads(
    const float* __restrict__ A, const float* __restrict__ B,
    int m0, int n0, int k0, uint32_t sA, uint32_t sB, int tid)
{
#pragma unroll
    for (int it = 0; it < 4; it++) {
        int idx = it * 256 + tid;
        int row = idx >> 3, c = idx & 7;
        CP_ASYNC16(sA + row * (GS * 4) + c * 16,
                   A + (size_t)(m0 + row) * CH + k0 + c * 4);
    }
#pragma unroll
    for (int it = 0; it < 4; it++) {
        int idx = it * 256 + tid;
        int row = idx >> 3, c = idx & 7;
        CP_ASYNC16(sB + row * (GS * 4) + c * 16,
                   B + (size_t)(n0 + row) * CH + k0 + c * 4);
    }
}

__device__ __forceinline__ void tf32_gemm_tile(
    const float* __restrict__ A, const float* __restrict__ B,
    int m0, int n0,
    float acc[4][4][4],
    uint32_t sbase, int tid)
{
    const int lane  = tid & 31;
    const int wid   = tid >> 5;
    const int wm    = wid & 1;
    const int wn    = wid >> 1;
    const int lane8 = lane & 7;
    const int laneh = (lane >> 3) & 1;
    const int laneq = lane >> 4;

    const uint32_t sA0 = sbase;
    const uint32_t sB0 = sbase + NSTAGE * GBUF * 4;

    const uint32_t a_lm =
        ((wm * 64 + lane8 + laneh * 8) * GS + laneq * 4) * 4;
    const uint32_t b_lm =
        ((wn * 32 + lane8) * GS + (lane >> 3) * 4) * 4;

    gemm_issue_loads(A, B, m0, n0, 0, sA0, sB0, tid);
    CP_COMMIT();
    gemm_issue_loads(A, B, m0, n0, 32, sA0 + GBUF * 4, sB0 + GBUF * 4, tid);
    CP_COMMIT();

    const int nk = CH / 32;
    int stage = 0;
    for (int ki = 0; ki < nk; ki++) {
        if (ki + 1 < nk) { CP_WAIT(1); } else { CP_WAIT(0); }
        __syncthreads();

        const uint32_t Ab = sA0 + stage * GBUF * 4;
        const uint32_t Bb = sB0 + stage * GBUF * 4;

        uint32_t af[2][4][4];
        uint32_t bf[4][4];
#pragma unroll
        for (int mt = 0; mt < 4; mt++)
            LDM_X4(af[0][mt], Ab + a_lm + mt * (16 * GS * 4));

#pragma unroll
        for (int kq = 0; kq < 4; kq++) {
            const int cur = kq & 1;
            if ((kq & 1) == 0) {
#pragma unroll
                for (int nt = 0; nt < 4; nt++)
                    LDM_X4(bf[nt], Bb + b_lm + nt * (8 * GS * 4) + (kq >> 1) * 64);
            }
            if (kq < 3) {
#pragma unroll
                for (int mt = 0; mt < 4; mt++)
                    LDM_X4(af[cur ^ 1][mt],
                           Ab + a_lm + mt * (16 * GS * 4) + (kq + 1) * 32);
            }
#pragma unroll
            for (int mt = 0; mt < 4; mt++)
#pragma unroll
                for (int nt = 0; nt < 4; nt++)
                    MMA_TF32(acc[mt][nt], af[cur][mt], &bf[nt][(kq & 1) * 2]);
        }

        if (ki + 2 < nk) {
            int ns = stage + 2 >= NSTAGE ? stage + 2 - NSTAGE : stage + 2;
            gemm_issue_loads(A, B, m0, n0, (ki + 2) * 32,
                             sA0 + ns * GBUF * 4, sB0 + ns * GBUF * 4, tid);
            CP_COMMIT();
        }
        stage = (stage + 1 == NSTAGE) ? 0 : stage + 1;
    }
}

// ---------------------------------------------------------------------------
// Kernel 1: QKV GEMM. Staged epilogue:
//  q/k: stage [m][EPS] (bias+scale+tf32), store 64-float d-runs coalesced.
//  v:   stage transposed [c][EPS], store 128-float t-runs coalesced.
// q carries the folded softmax*log2e scale (exp2 softmax downstream).
// ---------------------------------------------------------------------------
__global__ __launch_bounds__(256, 2) void qkv_gemm_kernel(
    const float* __restrict__ bias)
{
    extern __shared__ float smg[];
    const uint32_t sbase = smem_u32(smg);
    const int tid = threadIdx.x;
    const int m0 = blockIdx.y * 128;
    const int n0 = blockIdx.x * 128;

    float acc[4][4][4];
#pragma unroll
    for (int i = 0; i < 4; i++)
#pragma unroll
        for (int j = 0; j < 4; j++)
#pragma unroll
            for (int q = 0; q < 4; q++) acc[i][j][q] = 0.f;

    tf32_gemm_tile(g_x, g_wa, m0, n0, acc, sbase, tid);
    __syncthreads();   // mainloop smem reads done; safe to reuse for staging

    const int lane = tid & 31;
    const int wid  = tid >> 5;
    const int wm   = wid & 1;
    const int wn   = wid >> 1;
    const int lr   = lane >> 2;
    const int lc   = lane & 3;

    const int sec = n0 >> 10;  // 0=q 1=k 2=v
    const float scale = (sec == 0) ? 0.125f * LOG2E : 1.0f;
    const int bb = m0 >> 11;
    const int t0 = m0 & (SEQ - 1);

    if (sec < 2) {
        float* dst = (sec == 0) ? g_q : g_k;
        // stage [m][EPS]
#pragma unroll
        for (int mt = 0; mt < 4; mt++) {
            int rm = wm * 64 + mt * 16 + lr;
#pragma unroll
            for (int nt = 0; nt < 4; nt++) {
                int cc = wn * 32 + nt * 8 + lc * 2;
                float b0 = bias[n0 + cc], b1 = bias[n0 + cc + 1];
                *reinterpret_cast<float2*>(&smg[rm * EPS + cc]) =
                    make_float2(to_tf32((acc[mt][nt][0] + b0) * scale),
                                to_tf32((acc[mt][nt][1] + b1) * scale));
                *reinterpret_cast<float2*>(&smg[(rm + 8) * EPS + cc]) =
                    make_float2(to_tf32((acc[mt][nt][2] + b0) * scale),
                                to_tf32((acc[mt][nt][3] + b1) * scale));
            }
        }
        __syncthreads();
        const int h0 = (n0 & (CH - 1)) >> 6;
        const int l16 = lane & 15;
#pragma unroll
        for (int it = 0; it < 16; it++) {
            int seg = wid * 32 + it * 2 + (lane >> 4);
            int m = seg >> 1, half = seg & 1;
            float4 val = *reinterpret_cast<float4*>(&smg[m * EPS + half * 64 + l16 * 4]);
            float* p = dst +
                ((size_t)((bb * NHEAD + h0 + half) * SEQ + t0 + m)) * HDIM + l16 * 4;
            *reinterpret_cast<float4*>(p) = val;
        }
    } else {
        // v: stage transposed [c][EPS]
#pragma unroll
        for (int mt = 0; mt < 4; mt++) {
            int rm = wm * 64 + mt * 16 + lr;
#pragma unroll
            for (int nt = 0; nt < 4; nt++) {
                int cc = wn * 32 + nt * 8 + lc * 2;
                float b0 = bias[n0 + cc], b1 = bias[n0 + cc + 1];
                smg[cc * EPS + rm]           = to_tf32(acc[mt][nt][0] + b0);
                smg[(cc + 1) * EPS + rm]     = to_tf32(acc[mt][nt][1] + b1);
                smg[cc * EPS + rm + 8]       = to_tf32(acc[mt][nt][2] + b0);
                smg[(cc + 1) * EPS + rm + 8] = to_tf32(acc[mt][nt][3] + b1);
            }
        }
        __syncthreads();
#pragma unroll
        for (int it = 0; it < 16; it++) {
            int c = wid * 16 + it;
            float4 val = *reinterpret_cast<float4*>(&smg[c * EPS + lane * 4]);
            int n1 = (n0 + c) & (CH - 1);
            int h = n1 >> 6, d = n1 & 63;
            float* p = g_v +
                ((size_t)((bb * NHEAD + h) * HDIM + d)) * SEQ + t0 + lane * 4;
            *reinterpret_cast<float4*>(p) = val;
        }
    }
}

// ---------------------------------------------------------------------------
// Kernel 3: output projection; staged epilogue with coalesced row stores.
// ---------------------------------------------------------------------------
__global__ __launch_bounds__(256, 2) void proj_gemm_kernel(
    const float* __restrict__ bias, float* __restrict__ out)
{
    extern __shared__ float smg[];
    const uint32_t sbase = smem_u32(smg);
    const int tid = threadIdx.x;
    const int m0 = blockIdx.y * 128;
    const int n0 = blockIdx.x * 128;

    float acc[4][4][4];
#pragma unroll
    for (int i = 0; i < 4; i++)
#pragma unroll
        for (int j = 0; j < 4; j++)
#pragma unroll
            for (int q = 0; q < 4; q++) acc[i][j][q] = 0.f;

    tf32_gemm_tile(g_att, g_wp, m0, n0, acc, sbase, tid);
    __syncthreads();

    const int lane = tid & 31;
    const int wid  = tid >> 5;
    const int wm   = wid & 1;
    const int wn   = wid >> 1;
    const int lr   = lane >> 2;
    const int lc   = lane & 3;

#pragma unroll
    for (int mt = 0; mt < 4; mt++) {
        int rm = wm * 64 + mt * 16 + lr;
#pragma unroll
        for (int nt = 0; nt < 4; nt++) {
            int cc = wn * 32 + nt * 8 + lc * 2;
            float b0 = bias[n0 + cc], b1 = bias[n0 + cc + 1];
            *reinterpret_cast<float2*>(&smg[rm * EPS + cc]) =
                make_float2(acc[mt][nt][0] + b0, acc[mt][nt][1] + b1);
            *reinterpret_cast<float2*>(&smg[(rm + 8) * EPS + cc]) =
                make_float2(acc[mt][nt][2] + b0, acc[mt][nt][3] + b1);
        }
    }
    __syncthreads();
#pragma unroll
    for (int it = 0; it < 16; it++) {
        int m = wid * 16 + it;
        float4 val = *reinterpret_cast<float4*>(&smg[m * EPS + lane * 4]);
        *reinterpret_cast<float4*>(
            &out[(size_t)(m0 + m) * CH + n0 + lane * 4]) = val;
    }
}

// ---------------------------------------------------------------------------
// Kernel 2: causal flash attention (round-10 mbarrier pipeline) with exp2
// softmax (log2e folded into q at the QKV epilogue).
// ---------------------------------------------------------------------------
#define AST 68
#define KV_BUF (64 * AST)
#define ATTN_SMEM (((128 * AST + 4 * KV_BUF) * 4) + 32)

__device__ __forceinline__ void attn_issue_kv(
    const float* __restrict__ kp, const float* __restrict__ vp,
    int k0, uint32_t sK, uint32_t sV, int tid)
{
#pragma unroll
    for (int it = 0; it < 4; it++) {
        int idx = it * 256 + tid;
        int row = idx >> 4;
        int c4  = (idx & 15) * 4;
        CP_ASYNC16(sK + row * (AST * 4) + c4 * 4,
                   kp + (size_t)(k0 + row) * HDIM + c4);
        CP_ASYNC16(sV + row * (AST * 4) + c4 * 4,
                   vp + (size_t)row * SEQ + k0 + c4);
    }
}

__global__ __launch_bounds__(256, 2) void attn_kernel()
{
    extern __shared__ float sm[];
    const uint32_t sbase = smem_u32(sm);
    const uint32_t sQs = sbase;
    const uint32_t sKs = sbase + 128 * AST * 4;
    const uint32_t sVs = sKs + 2 * KV_BUF * 4;
    const uint32_t mbF = sVs + 2 * KV_BUF * 4;
    const uint32_t mbE = mbF + 16;

    const int tid   = threadIdx.x;
    const int lane  = tid & 31;
    const int wq    = tid >> 5;
    const int lr    = lane >> 2;
    const int lc    = lane & 3;
    const int lane8 = lane & 7;
    const int laneh = (lane >> 3) & 1;
    const int laneq = lane >> 4;

    const int qt = (int)gridDim.x - 1 - (int)blockIdx.x;
    const int bh = blockIdx.y;
    const int q0 = qt * 128;

    const float* qp = g_q + (size_t)bh * SEQ * HDIM;
    const float* kp = g_k + (size_t)bh * SEQ * HDIM;
    const float* vp = g_v + (size_t)bh * HDIM * SEQ;

    const uint32_t q_lm = sQs +
        ((wq * 16 + lane8 + laneh * 8) * AST + laneq * 4) * 4;
    const uint32_t k_lm = (lane8 * AST + (lane >> 3) * 4) * 4;
    const uint32_t p_lm = ((lane8 + laneh * 8) * AST + laneq * 4) * 4;
    const uint32_t v_lm = ((laneq * 8 + lane8) * AST + laneh * 4) * 4;

    if (tid == 0) {
        MBAR_INIT(mbF + 0, 256);
        MBAR_INIT(mbF + 8, 256);
        MBAR_INIT(mbE + 0, 8);
        MBAR_INIT(mbE + 8, 8);
    }
    __syncthreads();

#pragma unroll
    for (int it = 0; it < 8; it++) {
        int idx = it * 256 + tid;
        int row = idx >> 4;
        int c4  = (idx & 15) * 4;
        CP_ASYNC16(sQs + row * (AST * 4) + c4 * 4,
                   qp + (size_t)(q0 + row) * HDIM + c4);
    }
    attn_issue_kv(kp, vp, 0, sKs, sVs, tid);
    CPA_MBAR_ARRIVE(mbF + 0);
    attn_issue_kv(kp, vp, 64, sKs + KV_BUF * 4, sVs + KV_BUF * 4, tid);
    CPA_MBAR_ARRIVE(mbF + 8);

    uint32_t qf[8][4];
    const uint32_t sPt = sQs + wq * 16 * AST * 4;
    float* Pt = sm + wq * 16 * AST;

    float o[8][4] = {};
    float m0v = -1e30f, m1v = -1e30f;
    float l0v = 0.f, l1v = 0.f;

    const int nkt  = 2 * qt + 2;
    const int r_hi = q0 + wq * 16 + 15;

    for (int kt = 0; kt < nkt; kt++) {
        const int k0 = kt * 64;
        const uint32_t s  = (uint32_t)(kt & 1);
        const uint32_t cp = (uint32_t)((kt >> 1) & 1);

        if (kt >= 1 && kt + 1 < nkt) {
            const uint32_t so = s ^ 1u;
            mbar_wait(mbE + so * 8, (uint32_t)(((kt - 1) >> 1) & 1));
            attn_issue_kv(kp, vp, (kt + 1) * 64,
                          sKs + so * KV_BUF * 4, sVs + so * KV_BUF * 4, tid);
            CPA_MBAR_ARRIVE(mbF + so * 8);
        }

        mbar_wait(mbF + s * 8, cp);

        if (kt == 0) {
#pragma unroll
            for (int ss = 0; ss < 8; ss++)
                LDM_X4(qf[ss], q_lm + ss * 32);
        }

        if (k0 <= r_hi) {
            const uint32_t Kb = sKs + s * KV_BUF * 4;
            const uint32_t Vb = sVs + s * KV_BUF * 4;

            float sacc[8][4];
#pragma unroll
            for (int nt = 0; nt < 8; nt++)
#pragma unroll
                for (int q = 0; q < 4; q++) sacc[nt][q] = 0.f;

#pragma unroll
            for (int s2 = 0; s2 < 4; s2++) {
                uint32_t bf[8][4];
#pragma unroll
                for (int nt = 0; nt < 8; nt++)
                    LDM_X4(bf[nt], Kb + k_lm + nt * (8 * AST * 4) + s2 * 64);
#pragma unroll
                for (int sub = 0; sub < 2; sub++)
#pragma unroll
                    for (int nt = 0; nt < 8; nt++)
                        MMA_TF32(sacc[nt], qf[2 * s2 + sub], &bf[nt][sub * 2]);
            }

            if (kt >= 2 * qt) {
                int r0g = q0 + wq * 16 + lr;
#pragma unroll
                for (int nt = 0; nt < 8; nt++) {
                    int c0g = k0 + nt * 8 + 2 * lc;
                    if (c0g     > r0g)     sacc[nt][0] = -1e30f;
                    if (c0g + 1 > r0g)     sacc[nt][1] = -1e30f;
                    if (c0g     > r0g + 8) sacc[nt][2] = -1e30f;
                    if (c0g + 1 > r0g + 8) sacc[nt][3] = -1e30f;
                }
            }

            float rm0 = -1e30f, rm1 = -1e30f;
#pragma unroll
            for (int nt = 0; nt < 8; nt++) {
                rm0 = fmaxf(rm0, fmaxf(sacc[nt][0], sacc[nt][1]));
                rm1 = fmaxf(rm1, fmaxf(sacc[nt][2], sacc[nt][3]));
            }
            rm0 = fmaxf(rm0, __shfl_xor_sync(0xffffffffu, rm0, 1));
            rm0 = fmaxf(rm0, __shfl_xor_sync(0xffffffffu, rm0, 2));
            rm1 = fmaxf(rm1, __shfl_xor_sync(0xffffffffu, rm1, 1));
            rm1 = fmaxf(rm1, __shfl_xor_sync(0xffffffffu, rm1, 2));

            float mn0 = fmaxf(m0v, rm0);
            float mn1 = fmaxf(m1v, rm1);
            float cr0 = exp2f(m0v - mn0);
            float cr1 = exp2f(m1v - mn1);
            m0v = mn0; m1v = mn1;

            float rs0 = 0.f, rs1 = 0.f;
#pragma unroll
            for (int nt = 0; nt < 8; nt++) {
                sacc[nt][0] = exp2f(sacc[nt][0] - mn0);
                sacc[nt][1] = exp2f(sacc[nt][1] - mn0);
                sacc[nt][2] = exp2f(sacc[nt][2] - mn1);
                sacc[nt][3] = exp2f(sacc[nt][3] - mn1);
                rs0 += sacc[nt][0] + sacc[nt][1];
                rs1 += sacc[nt][2] + sacc[nt][3];
            }
            rs0 += __shfl_xor_sync(0xffffffffu, rs0, 1);
            rs0 += __shfl_xor_sync(0xffffffffu, rs0, 2);
            rs1 += __shfl_xor_sync(0xffffffffu, rs1, 1);
            rs1 += __shfl_xor_sync(0xffffffffu, rs1, 2);
            l0v = l0v * cr0 + rs0;
            l1v = l1v * cr1 + rs1;
#pragma unroll
            for (int nt = 0; nt < 8; nt++) {
                o[nt][0] *= cr0; o[nt][1] *= cr0;
                o[nt][2] *= cr1; o[nt][3] *= cr1;
            }

#pragma unroll
            for (int nt = 0; nt < 8; nt++) {
                *reinterpret_cast<float2*>(&Pt[lr * AST + nt * 8 + 2 * lc]) =
                    make_float2(to_tf32(sacc[nt][0]), to_tf32(sacc[nt][1]));
                *reinterpret_cast<float2*>(&Pt[(lr + 8) * AST + nt * 8 + 2 * lc]) =
                    make_float2(to_tf32(sacc[nt][2]), to_tf32(sacc[nt][3]));
            }
            __syncwarp();

#pragma unroll
            for (int ss = 0; ss < 8; ss++) {
                uint32_t a[4];
                LDM_X4(a, sPt + p_lm + ss * 32);
#pragma unroll
                for (int dp = 0; dp < 4; dp++) {
                    uint32_t b[4];
                    LDM_X4(b, Vb + v_lm + dp * (16 * AST * 4) + ss * 32);
                    MMA_TF32(o[2 * dp],     a, &b[0]);
                    MMA_TF32(o[2 * dp + 1], a, &b[2]);
                }
            }
        }

        __syncwarp();
        if (lane == 0) MBAR_ARRIVE(mbE + s * 8);
    }

    const int b = bh >> 4, h = bh & 15;
    const int r0g = q0 + wq * 16 + lr;
    const float inv0 = 1.0f / l0v;
    const float inv1 = 1.0f / l1v;
#pragma unroll
    for (int nt = 0; nt < 8; nt++) {
        int cg = h * 64 + nt * 8 + 2 * lc;
        *reinterpret_cast<float2*>(&g_att[(size_t)(b * SEQ + r0g) * CH + cg]) =
            make_float2(to_tf32(o[nt][0] * inv0), to_tf32(o[nt][1] * inv0));
        *reinterpret_cast<float2*>(&g_att[(size_t)(b * SEQ + r0g + 8) * CH + cg]) =
            make_float2(to_tf32(o[nt][2] * inv1), to_tf32(o[nt][3] * inv1));
    }
}

// ---------------------------------------------------------------------------
extern "C" void kernel_launch(void* const* d_in, const int* in_sizes, int n_in,
                              void* d_out, int out_size)
{
    const float* x      = (const float*)d_in[0];
    const float* w_attn = (const float*)d_in[1];
    const float* b_attn = (const float*)d_in[2];
    const float* w_proj = (const float*)d_in[3];
    const float* b_proj = (const float*)d_in[4];
    float* out = (float*)d_out;

    cudaFuncSetAttribute(qkv_gemm_kernel,
                         cudaFuncAttributeMaxDynamicSharedMemorySize, GEMM_SMEM);
    cudaFuncSetAttribute(proj_gemm_kernel,
                         cudaFuncAttributeMaxDynamicSharedMemorySize, GEMM_SMEM);
    cudaFuncSetAttribute(attn_kernel,
                         cudaFuncAttributeMaxDynamicSharedMemorySize, ATTN_SMEM);

    // 0) tf32-round x; transpose+round weights to [N][K]
    cvt_x_kernel<<<(BATCH * SEQ * CH / 4 + 255) / 256, 256>>>(x,
        BATCH * SEQ * CH / 4);
    cvt_T_kernel<<<dim3(3 * CH / 32, CH / 32), dim3(32, 8)>>>(w_attn, 1, 3 * CH);
    cvt_T_kernel<<<dim3(CH / 32, CH / 32), dim3(32, 8)>>>(w_proj, 2, CH);

    // 1) QKV GEMM: grid (3072/128, 8192/128)
    qkv_gemm_kernel<<<dim3(24, 64), 256, GEMM_SMEM>>>(b_attn);

    // 2) Attention: grid (16 q-tiles, B*NH)
    attn_kernel<<<dim3(16, BATCH * NHEAD), 256, ATTN_SMEM>>>();

    // 3) Projection: grid (1024/128, 8192/128)
    proj_gemm_kernel<<<dim3(8, 64), 256, GEMM_SMEM>>>(b_proj, out);
}

// round 12
// speedup vs baseline: 1.8747x; 1.8747x over previous
#include <cuda_runtime.h>
#include <cuda_fp16.h>
#include <cstdint>

#define BATCH 4
#define SEQ   2048
#define CH    1024
#define NHEAD 16
#define HDIM  64
#define LOG2E 1.4426950408889634f

// Scratch (allocation-free rule: __device__ globals). All operands fp16.
// q,k: [b,h,t,d]; v: [b,h,d,t] (transposed for PV ldmatrix).
__device__ __half g_q16[BATCH * NHEAD * SEQ * HDIM];
__device__ __half g_k16[BATCH * NHEAD * SEQ * HDIM];
__device__ __half g_v16[BATCH * NHEAD * HDIM * SEQ];
__device__ __half g_att16[BATCH * SEQ * CH];     // [b,t,c]
__device__ __half g_x16 [BATCH * SEQ * CH];      // x
__device__ __half g_wa16[3 * CH * CH];           // w_attn^T: [3072][1024]
__device__ __half g_wp16[CH * CH];               // w_proj^T: [1024][1024]

#define MMA_F16(d, a, b)                                                   \
    asm volatile(                                                          \
        "mma.sync.aligned.m16n8k16.row.col.f32.f16.f16.f32 "               \
        "{%0,%1,%2,%3},{%4,%5,%6,%7},{%8,%9},{%0,%1,%2,%3};"               \
        : "+f"((d)[0]), "+f"((d)[1]), "+f"((d)[2]), "+f"((d)[3])           \
        : "r"((a)[0]), "r"((a)[1]), "r"((a)[2]), "r"((a)[3]),              \
          "r"((b)[0]), "r"((b)[1]))

#define LDM_X4(r, addr)                                                    \
    asm volatile("ldmatrix.sync.aligned.m8n8.x4.shared.b16 "               \
                 "{%0,%1,%2,%3}, [%4];"                                    \
                 : "=r"((r)[0]), "=r"((r)[1]), "=r"((r)[2]), "=r"((r)[3])  \
                 : "r"(addr))

#define CP_ASYNC16(dst_u32, src_ptr)                                       \
    asm volatile("cp.async.cg.shared.global [%0], [%1], 16;"               \
                 :: "r"(dst_u32), "l"(src_ptr))
#define CP_COMMIT() asm volatile("cp.async.commit_group;")
#define CP_WAIT(N)  asm volatile("cp.async.wait_group %0;" :: "n"(N))

#define MBAR_INIT(addr, cnt)                                               \
    asm volatile("mbarrier.init.shared::cta.b64 [%0], %1;"                 \
                 :: "r"(addr), "r"((uint32_t)(cnt)) : "memory")
#define MBAR_ARRIVE(addr)                                                  \
    asm volatile("{\n\t.reg .b64 t;\n\t"                                   \
                 "mbarrier.arrive.shared::cta.b64 t, [%0];\n\t}"           \
                 :: "r"(addr) : "memory")
#define CPA_MBAR_ARRIVE(addr)                                              \
    asm volatile("cp.async.mbarrier.arrive.noinc.shared::cta.b64 [%0];"    \
                 :: "r"(addr) : "memory")

__device__ __forceinline__ void mbar_wait(uint32_t mbar, uint32_t parity) {
    asm volatile(
        "{\n\t.reg .pred P;\n\t"
        "W_%=:\n\t"
        "mbarrier.try_wait.parity.acquire.cta.shared::cta.b64 P, [%0], %1, 0x989680;\n\t"
        "@!P bra W_%=;\n\t"
        "}" :: "r"(mbar), "r"(parity) : "memory");
}

__device__ __forceinline__ uint32_t smem_u32(const void* p) {
    return (uint32_t)__cvta_generic_to_shared(p);
}

// ---------------------------------------------------------------------------
// Prologue converts (fp32 -> fp16)
// ---------------------------------------------------------------------------
__global__ void cvt_x_kernel(const float* __restrict__ src, int n4)
{
    int i = blockIdx.x * blockDim.x + threadIdx.x;
    if (i < n4) {
        float4 v = reinterpret_cast<const float4*>(src)[i];
        __half2 h0 = __floats2half2_rn(v.x, v.y);
        __half2 h1 = __floats2half2_rn(v.z, v.w);
        reinterpret_cast<__half2*>(g_x16)[2 * i]     = h0;
        reinterpret_cast<__half2*>(g_x16)[2 * i + 1] = h1;
    }
}

// Transpose + fp16: src [CH][N] -> dst [N][CH]
__global__ void cvt_T_kernel(const float* __restrict__ src, int sel, int N)
{
    __shared__ float tile[32][33];
    __half* dst = (sel == 1) ? g_wa16 : g_wp16;
    int n0 = blockIdx.x * 32, k0 = blockIdx.y * 32;
    int tx = threadIdx.x, ty = threadIdx.y;  // 32 x 8
#pragma unroll
    for (int i = 0; i < 4; i++)
        tile[ty + 8 * i][tx] = src[(size_t)(k0 + ty + 8 * i) * N + n0 + tx];
    __syncthreads();
#pragma unroll
    for (int i = 0; i < 2; i++) {
        int nl = ty + i * 8 + (tx >> 4) * 16;
        int kc = (tx & 15) * 2;
        __half2 h = __floats2half2_rn(tile[kc][nl], tile[kc + 1][nl]);
        *reinterpret_cast<__half2*>(dst + (size_t)(n0 + nl) * CH + k0 + kc) = h;
    }
}

// ---------------------------------------------------------------------------
// FP16 GEMM core: block 128x128, BK=64, 8 warps (2x4), warp tile 64x32.
// A smem [128][72] halves (m rows, k contig); B smem [128][72] (n rows).
// 3-stage cp.async pipeline + register double-buffered A fragments.
// ---------------------------------------------------------------------------
#define GP 72                        // smem pitch (halves); 144B rows
#define GROWB (GP * 2)               // 144 bytes per row
#define GBUFB (128 * GROWB)          // 18432 bytes per operand buffer
#define NSTAGE 3
#define GEMM_SMEM (2 * NSTAGE * GBUFB)   // 110592 B

__device__ __forceinline__ void gemm_issue_loads(
    const __half* __restrict__ A, const __half* __restrict__ B,
    int m0, int n0, int k0, uint32_t sA, uint32_t sB, int tid)
{
#pragma unroll
    for (int it = 0; it < 4; it++) {
        int idx = it * 256 + tid;
        int row = idx >> 3, c = idx & 7;
        CP_ASYNC16(sA + row * GROWB + c * 16,
                   A + (size_t)(m0 + row) * CH + k0 + c * 8);
    }
#pragma unroll
    for (int it = 0; it < 4; it++) {
        int idx = it * 256 + tid;
        int row = idx >> 3, c = idx & 7;
        CP_ASYNC16(sB + row * GROWB + c * 16,
                   B + (size_t)(n0 + row) * CH + k0 + c * 8);
    }
}

__device__ __forceinline__ void f16_gemm_tile(
    const __half* __restrict__ A, const __half* __restrict__ B,
    int m0, int n0,
    float acc[4][4][4],
    uint32_t sbase, int tid)
{
    const int lane  = tid & 31;
    const int wid   = tid >> 5;
    const int wm    = wid & 1;
    const int wn    = wid >> 1;
    const int l16   = lane & 15;
    const int lane8 = lane & 7;

    const uint32_t sA0 = sbase;
    const uint32_t sB0 = sbase + NSTAGE * GBUFB;

    // ldmatrix per-lane byte offsets within a buffer
    const uint32_t a_lm =
        ((wm * 64 + l16) * GP + (lane >> 4) * 8) * 2;            // +mt*2304 +ks*32
    const uint32_t b_lm =
        ((wn * 32 + (lane >> 4) * 8 + lane8) * GP +
         ((lane >> 3) & 1) * 8) * 2;                             // +nt2*2304 +ks*32

    gemm_issue_loads(A, B, m0, n0, 0, sA0, sB0, tid);
    CP_COMMIT();
    gemm_issue_loads(A, B, m0, n0, 64, sA0 + GBUFB, sB0 + GBUFB, tid);
    CP_COMMIT();

    const int nk = CH / 64;   // 16
    int stage = 0;
    for (int ki = 0; ki < nk; ki++) {
        if (ki + 1 < nk) { CP_WAIT(1); } else { CP_WAIT(0); }
        __syncthreads();

        const uint32_t Ab = sA0 + stage * GBUFB;
        const uint32_t Bb = sB0 + stage * GBUFB;

        uint32_t af[2][4][4];
#pragma unroll
        for (int mt = 0; mt < 4; mt++)
            LDM_X4(af[0][mt], Ab + a_lm + mt * 2304);   // ks=0

#pragma unroll
        for (int ks = 0; ks < 4; ks++) {
            const int cur = ks & 1;
            uint32_t bf[2][4];
            LDM_X4(bf[0], Bb + b_lm + ks * 32);
            LDM_X4(bf[1], Bb + b_lm + 2304 + ks * 32);
            if (ks < 3) {
#pragma unroll
                for (int mt = 0; mt < 4; mt++)
                    LDM_X4(af[cur ^ 1][mt],
                           Ab + a_lm + mt * 2304 + (ks + 1) * 32);
            }
#pragma unroll
            for (int mt = 0; mt < 4; mt++) {
#pragma unroll
                for (int nt2 = 0; nt2 < 2; nt2++) {
                    MMA_F16(acc[mt][2 * nt2],     af[cur][mt], &bf[nt2][0]);
                    MMA_F16(acc[mt][2 * nt2 + 1], af[cur][mt], &bf[nt2][2]);
                }
            }
        }

        if (ki + 2 < nk) {
            int ns = stage + 2 >= NSTAGE ? stage + 2 - NSTAGE : stage + 2;
            gemm_issue_loads(A, B, m0, n0, (ki + 2) * 64,
                             sA0 + ns * GBUFB, sB0 + ns * GBUFB, tid);
            CP_COMMIT();
        }
        stage = (stage + 1 == NSTAGE) ? 0 : stage + 1;
    }
}

// ---------------------------------------------------------------------------
// Kernel 1: QKV GEMM. q/k direct half2 stores [b,h,t,d]; v staged through
// smem (transposed) then coalesced 16B stores into [b,h,d,t].
// q carries folded softmax*log2e scale.
// ---------------------------------------------------------------------------
#define VPS 144   // v-staging pitch (halves); rows 288B (16B-aligned)

__global__ __launch_bounds__(256, 2) void qkv_gemm_kernel(
    const float* __restrict__ bias)
{
    extern __shared__ float smg[];
    const uint32_t sbase = smem_u32(smg);
    const int tid = threadIdx.x;
    const int m0 = blockIdx.y * 128;
    const int n0 = blockIdx.x * 128;

    float acc[4][4][4];
#pragma unroll
    for (int i = 0; i < 4; i++)
#pragma unroll
        for (int j = 0; j < 4; j++)
#pragma unroll
            for (int q = 0; q < 4; q++) acc[i][j][q] = 0.f;

    f16_gemm_tile(g_x16, g_wa16, m0, n0, acc, sbase, tid);
    __syncthreads();   // smem free for v staging

    const int lane = tid & 31;
    const int wid  = tid >> 5;
    const int wm   = wid & 1;
    const int wn   = wid >> 1;
    const int lr   = lane >> 2;
    const int lc   = lane & 3;

    const int sec = n0 >> 10;  // 0=q 1=k 2=v
    const float scale = (sec == 0) ? 0.125f * LOG2E : 1.0f;
    const int bb = m0 >> 11;
    const int t0 = m0 & (SEQ - 1);

    if (sec < 2) {
        __half* dst = (sec == 0) ? g_q16 : g_k16;
#pragma unroll
        for (int mt = 0; mt < 4; mt++) {
            int t = t0 + wm * 64 + mt * 16 + lr;
#pragma unroll
            for (int nt = 0; nt < 4; nt++) {
                int c0 = n0 + wn * 32 + nt * 8 + lc * 2;
                float b0 = bias[c0], b1 = bias[c0 + 1];
                int n1 = c0 & (CH - 1);
                int h  = n1 >> 6;
                int d  = n1 & 63;
                __half* p = dst + ((size_t)((bb * NHEAD + h) * SEQ + t)) * HDIM + d;
                *reinterpret_cast<__half2*>(p) =
                    __floats2half2_rn((acc[mt][nt][0] + b0) * scale,
                                      (acc[mt][nt][1] + b1) * scale);
                *reinterpret_cast<__half2*>(p + 8 * HDIM) =
                    __floats2half2_rn((acc[mt][nt][2] + b0) * scale,
                                      (acc[mt][nt][3] + b1) * scale);
            }
        }
    } else {
        // v: stage transposed [c][VPS] halves, then coalesced t-runs
        __half* smh = reinterpret_cast<__half*>(smg);
#pragma unroll
        for (int mt = 0; mt < 4; mt++) {
            int rm = wm * 64 + mt * 16 + lr;
#pragma unroll
            for (int nt = 0; nt < 4; nt++) {
                int cc = wn * 32 + nt * 8 + lc * 2;
                float b0 = bias[n0 + cc], b1 = bias[n0 + cc + 1];
                smh[cc * VPS + rm]           = __float2half_rn(acc[mt][nt][0] + b0);
                smh[(cc + 1) * VPS + rm]     = __float2half_rn(acc[mt][nt][1] + b1);
                smh[cc * VPS + rm + 8]       = __float2half_rn(acc[mt][nt][2] + b0);
                smh[(cc + 1) * VPS + rm + 8] = __float2half_rn(acc[mt][nt][3] + b1);
            }
        }
        __syncthreads();
        const int l16 = lane & 15;
#pragma unroll
        for (int it = 0; it < 8; it++) {
            int c = wid * 16 + it * 2 + (lane >> 4);
            uint4 val = *reinterpret_cast<uint4*>(&smh[c * VPS + l16 * 8]);
            int n1 = (n0 + c) & (CH - 1);
            int h = n1 >> 6, d = n1 & 63;
            __half* p = g_v16 +
                ((size_t)((bb * NHEAD + h) * HDIM + d)) * SEQ + t0 + l16 * 8;
            *reinterpret_cast<uint4*>(p) = val;
        }
    }
}

// ---------------------------------------------------------------------------
// Kernel 3: output projection (fp32 out, direct float2 stores)
// ---------------------------------------------------------------------------
__global__ __launch_bounds__(256, 2) void proj_gemm_kernel(
    const float* __restrict__ bias, float* __restrict__ out)
{
    extern __shared__ float smg[];
    const uint32_t sbase = smem_u32(smg);
    const int tid = threadIdx.x;
    const int m0 = blockIdx.y * 128;
    const int n0 = blockIdx.x * 128;

    float acc[4][4][4];
#pragma unroll
    for (int i = 0; i < 4; i++)
#pragma unroll
        for (int j = 0; j < 4; j++)
#pragma unroll
            for (int q = 0; q < 4; q++) acc[i][j][q] = 0.f;

    f16_gemm_tile(g_att16, g_wp16, m0, n0, acc, sbase, tid);

    const int lane = tid & 31;
    const int wid  = tid >> 5;
    const int wm   = wid & 1;
    const int wn   = wid >> 1;
    const int lr   = lane >> 2;
    const int lc   = lane & 3;

#pragma unroll
    for (int mt = 0; mt < 4; mt++) {
        int r0 = m0 + wm * 64 + mt * 16 + lr;
#pragma unroll
        for (int nt = 0; nt < 4; nt++) {
            int c0 = n0 + wn * 32 + nt * 8 + lc * 2;
            float b0 = bias[c0], b1 = bias[c0 + 1];
            *reinterpret_cast<float2*>(&out[(size_t)r0 * CH + c0]) =
                make_float2(acc[mt][nt][0] + b0, acc[mt][nt][1] + b1);
            *reinterpret_cast<float2*>(&out[(size_t)(r0 + 8) * CH + c0]) =
                make_float2(acc[mt][nt][2] + b0, acc[mt][nt][3] + b1);
        }
    }
}

// ---------------------------------------------------------------------------
// Kernel 2: causal flash attention, fp16 mma m16n8k16, round-10 mbarrier
// pipeline, exp2 softmax (log2e folded into q).
// Block: 128 q x 64 kv; 8 warps x 16 q rows. K smem [t][72]h, V [d][72]h.
// ---------------------------------------------------------------------------
#define AP 72                         // attention smem pitch (halves)
#define AROWB (AP * 2)                // 144 B
#define QBUFB (128 * AROWB)           // 18432 B
#define KVBUFB (64 * AROWB)           // 9216 B
#define ATTN_SMEM (QBUFB + 4 * KVBUFB + 32)

__device__ __forceinline__ void attn_issue_kv(
    const __half* __restrict__ kp, const __half* __restrict__ vp,
    int k0, uint32_t sK, uint32_t sV, int tid)
{
#pragma unroll
    for (int it = 0; it < 2; it++) {
        int idx = it * 256 + tid;
        int row = idx >> 3;
        int c   = idx & 7;
        CP_ASYNC16(sK + row * AROWB + c * 16,
                   kp + (size_t)(k0 + row) * HDIM + c * 8);
        CP_ASYNC16(sV + row * AROWB + c * 16,
                   vp + (size_t)row * SEQ + k0 + c * 8);
    }
}

__global__ __launch_bounds__(256, 2) void attn_kernel()
{
    extern __shared__ float sm[];
    const uint32_t sbase = smem_u32(sm);
    const uint32_t sQs = sbase;
    const uint32_t sKs = sbase + QBUFB;
    const uint32_t sVs = sKs + 2 * KVBUFB;
    const uint32_t mbF = sVs + 2 * KVBUFB;
    const uint32_t mbE = mbF + 16;

    const int tid   = threadIdx.x;
    const int lane  = tid & 31;
    const int wq    = tid >> 5;
    const int lr    = lane >> 2;
    const int lc    = lane & 3;
    const int l16   = lane & 15;
    const int lane8 = lane & 7;

    const int qt = (int)gridDim.x - 1 - (int)blockIdx.x;  // big tiles first
    const int bh = blockIdx.y;
    const int q0 = qt * 128;

    const __half* qp = g_q16 + (size_t)bh * SEQ * HDIM;
    const __half* kp = g_k16 + (size_t)bh * SEQ * HDIM;
    const __half* vp = g_v16 + (size_t)bh * HDIM * SEQ;

    // ldmatrix per-lane byte offsets
    const uint32_t q_lm = sQs +
        ((wq * 16 + l16) * AP + (lane >> 4) * 8) * 2;               // +ks*32
    const uint32_t kv_lm =
        (((lane >> 4) * 8 + lane8) * AP + ((lane >> 3) & 1) * 8) * 2; // +nt2*2304 +ks*32
    const uint32_t p_lm = (l16 * AP + (lane >> 4) * 8) * 2;          // +ks*32

    if (tid == 0) {
        MBAR_INIT(mbF + 0, 256);
        MBAR_INIT(mbF + 8, 256);
        MBAR_INIT(mbE + 0, 8);
        MBAR_INIT(mbE + 8, 8);
    }
    __syncthreads();

    // Prologue: Q tile + kv tiles 0 and 1.
#pragma unroll
    for (int it = 0; it < 4; it++) {
        int idx = it * 256 + tid;
        int row = idx >> 3;
        int c   = idx & 7;
        CP_ASYNC16(sQs + row * AROWB + c * 16,
                   qp + (size_t)(q0 + row) * HDIM + c * 8);
    }
    attn_issue_kv(kp, vp, 0, sKs, sVs, tid);
    CPA_MBAR_ARRIVE(mbF + 0);
    attn_issue_kv(kp, vp, 64, sKs + KVBUFB, sVs + KVBUFB, tid);
    CPA_MBAR_ARRIVE(mbF + 8);

    uint32_t qf[4][4];
    const uint32_t sPt = sQs + wq * 16 * AROWB;      // per-warp 16x64 half slab
    __half* Pt = reinterpret_cast<__half*>(sm) + wq * 16 * AP;

    float o[8][4] = {};
    float m0v = -1e30f, m1v = -1e30f;
    float l0v = 0.f, l1v = 0.f;

    const int nkt  = 2 * qt + 2;
    const int r_hi = q0 + wq * 16 + 15;

    for (int kt = 0; kt < nkt; kt++) {
        const int k0 = kt * 64;
        const uint32_t s  = (uint32_t)(kt & 1);
        const uint32_t cp = (uint32_t)((kt >> 1) & 1);

        if (kt >= 1 && kt + 1 < nkt) {
            const uint32_t so = s ^ 1u;
            mbar_wait(mbE + so * 8, (uint32_t)(((kt - 1) >> 1) & 1));
            attn_issue_kv(kp, vp, (kt + 1) * 64,
                          sKs + so * KVBUFB, sVs + so * KVBUFB, tid);
            CPA_MBAR_ARRIVE(mbF + so * 8);
        }

        mbar_wait(mbF + s * 8, cp);

        if (kt == 0) {
#pragma unroll
            for (int ks = 0; ks < 4; ks++)
                LDM_X4(qf[ks], q_lm + ks * 32);
        }

        if (k0 <= r_hi) {
            const uint32_t Kb = sKs + s * KVBUFB;
            const uint32_t Vb = sVs + s * KVBUFB;

            // ---- S = Q @ K^T : 32 mmas ----
            float sacc[8][4];
#pragma unroll
            for (int nt = 0; nt < 8; nt++)
#pragma unroll
                for (int q = 0; q < 4; q++) sacc[nt][q] = 0.f;

#pragma unroll
            for (int ks = 0; ks < 4; ks++) {
#pragma unroll
                for (int nt2 = 0; nt2 < 4; nt2++) {
                    uint32_t bf[4];
                    LDM_X4(bf, Kb + kv_lm + nt2 * 2304 + ks * 32);
                    MMA_F16(sacc[2 * nt2],     qf[ks], &bf[0]);
                    MMA_F16(sacc[2 * nt2 + 1], qf[ks], &bf[2]);
                }
            }

            // ---- causal mask ----
            if (kt >= 2 * qt) {
                int r0g = q0 + wq * 16 + lr;
#pragma unroll
                for (int nt = 0; nt < 8; nt++) {
                    int c0g = k0 + nt * 8 + 2 * lc;
                    if (c0g     > r0g)     sacc[nt][0] = -1e30f;
                    if (c0g + 1 > r0g)     sacc[nt][1] = -1e30f;
                    if (c0g     > r0g + 8) sacc[nt][2] = -1e30f;
                    if (c0g + 1 > r0g + 8) sacc[nt][3] = -1e30f;
                }
            }

            // ---- online softmax (exp2) ----
            float rm0 = -1e30f, rm1 = -1e30f;
#pragma unroll
            for (int nt = 0; nt < 8; nt++) {
                rm0 = fmaxf(rm0, fmaxf(sacc[nt][0], sacc[nt][1]));
                rm1 = fmaxf(rm1, fmaxf(sacc[nt][2], sacc[nt][3]));
            }
            rm0 = fmaxf(rm0, __shfl_xor_sync(0xffffffffu, rm0, 1));
            rm0 = fmaxf(rm0, __shfl_xor_sync(0xffffffffu, rm0, 2));
            rm1 = fmaxf(rm1, __shfl_xor_sync(0xffffffffu, rm1, 1));
            rm1 = fmaxf(rm1, __shfl_xor_sync(0xffffffffu, rm1, 2));

            float mn0 = fmaxf(m0v, rm0);
            float mn1 = fmaxf(m1v, rm1);
            float cr0 = exp2f(m0v - mn0);
            float cr1 = exp2f(m1v - mn1);
            m0v = mn0; m1v = mn1;

            float rs0 = 0.f, rs1 = 0.f;
#pragma unroll
            for (int nt = 0; nt < 8; nt++) {
                sacc[nt][0] = exp2f(sacc[nt][0] - mn0);
                sacc[nt][1] = exp2f(sacc[nt][1] - mn0);
                sacc[nt][2] = exp2f(sacc[nt][2] - mn1);
                sacc[nt][3] = exp2f(sacc[nt][3] - mn1);
                rs0 += sacc[nt][0] + sacc[nt][1];
                rs1 += sacc[nt][2] + sacc[nt][3];
            }
            rs0 += __shfl_xor_sync(0xffffffffu, rs0, 1);
            rs0 += __shfl_xor_sync(0xffffffffu, rs0, 2);
            rs1 += __shfl_xor_sync(0xffffffffu, rs1, 1);
            rs1 += __shfl_xor_sync(0xffffffffu, rs1, 2);
            l0v = l0v * cr0 + rs0;
            l1v = l1v * cr1 + rs1;
#pragma unroll
            for (int nt = 0; nt < 8; nt++) {
                o[nt][0] *= cr0; o[nt][1] *= cr0;
                o[nt][2] *= cr1; o[nt][3] *= cr1;
            }

            // ---- P -> per-warp smem slab (fp16) ----
#pragma unroll
            for (int nt = 0; nt < 8; nt++) {
                *reinterpret_cast<__half2*>(&Pt[lr * AP + nt * 8 + 2 * lc]) =
                    __floats2half2_rn(sacc[nt][0], sacc[nt][1]);
                *reinterpret_cast<__half2*>(&Pt[(lr + 8) * AP + nt * 8 + 2 * lc]) =
                    __floats2half2_rn(sacc[nt][2], sacc[nt][3]);
            }
            __syncwarp();

            // ---- O += P @ V : 32 mmas ----
#pragma unroll
            for (int ks = 0; ks < 4; ks++) {
                uint32_t a[4];
                LDM_X4(a, sPt + p_lm + ks * 32);
#pragma unroll
                for (int nt2 = 0; nt2 < 4; nt2++) {
                    uint32_t b[4];
                    LDM_X4(b, Vb + kv_lm + nt2 * 2304 + ks * 32);
                    MMA_F16(o[2 * nt2],     a, &b[0]);
                    MMA_F16(o[2 * nt2 + 1], a, &b[2]);
                }
            }
        }

        __syncwarp();
        if (lane == 0) MBAR_ARRIVE(mbE + s * 8);
    }

    // ---- normalize + store to [b,t,c] (fp16: feeds proj) ----
    const int b = bh >> 4, h = bh & 15;
    const int r0g = q0 + wq * 16 + lr;
    const float inv0 = 1.0f / l0v;
    const float inv1 = 1.0f / l1v;
#pragma unroll
    for (int nt = 0; nt < 8; nt++) {
        int cg = h * 64 + nt * 8 + 2 * lc;
        *reinterpret_cast<__half2*>(
            &g_att16[(size_t)(b * SEQ + r0g) * CH + cg]) =
            __floats2half2_rn(o[nt][0] * inv0, o[nt][1] * inv0);
        *reinterpret_cast<__half2*>(
            &g_att16[(size_t)(b * SEQ + r0g + 8) * CH + cg]) =
            __floats2half2_rn(o[nt][2] * inv1, o[nt][3] * inv1);
    }
}

// ---------------------------------------------------------------------------
extern "C" void kernel_launch(void* const* d_in, const int* in_sizes, int n_in,
                              void* d_out, int out_size)
{
    const float* x      = (const float*)d_in[0];
    const float* w_attn = (const float*)d_in[1];
    const float* b_attn = (const float*)d_in[2];
    const float* w_proj = (const float*)d_in[3];
    const float* b_proj = (const float*)d_in[4];
    float* out = (float*)d_out;

    cudaFuncSetAttribute(qkv_gemm_kernel,
                         cudaFuncAttributeMaxDynamicSharedMemorySize, GEMM_SMEM);
    cudaFuncSetAttribute(proj_gemm_kernel,
                         cudaFuncAttributeMaxDynamicSharedMemorySize, GEMM_SMEM);
    cudaFuncSetAttribute(attn_kernel,
                         cudaFuncAttributeMaxDynamicSharedMemorySize, ATTN_SMEM);

    // 0) fp16-convert x; transpose+convert weights to [N][K]
    cvt_x_kernel<<<(BATCH * SEQ * CH / 4 + 255) / 256, 256>>>(x,
        BATCH * SEQ * CH / 4);
    cvt_T_kernel<<<dim3(3 * CH / 32, CH / 32), dim3(32, 8)>>>(w_attn, 1, 3 * CH);
    cvt_T_kernel<<<dim3(CH / 32, CH / 32), dim3(32, 8)>>>(w_proj, 2, CH);

    // 1) QKV GEMM: grid (3072/128, 8192/128)
    qkv_gemm_kernel<<<dim3(24, 64), 256, GEMM_SMEM>>>(b_attn);

    // 2) Attention: grid (16 q-tiles, B*NH)
    attn_kernel<<<dim3(16, BATCH * NHEAD), 256, ATTN_SMEM>>>();

    // 3) Projection: grid (1024/128, 8192/128)
    proj_gemm_kernel<<<dim3(8, 64), 256, GEMM_SMEM>>>(b_proj, out);
}

// round 13
// speedup vs baseline: 1.9589x; 1.0450x over previous
#include <cuda_runtime.h>
#include <cuda_fp16.h>
#include <cstdint>

#define BATCH 4
#define SEQ   2048
#define CH    1024
#define NHEAD 16
#define HDIM  64
#define LOG2E 1.4426950408889634f

// Scratch (allocation-free rule: __device__ globals). All operands fp16.
// q,k: [b,h,t,d]; v: [b,h,d,t] (transposed for PV ldmatrix).
__device__ __half g_q16[BATCH * NHEAD * SEQ * HDIM];
__device__ __half g_k16[BATCH * NHEAD * SEQ * HDIM];
__device__ __half g_v16[BATCH * NHEAD * HDIM * SEQ];
__device__ __half g_att16[BATCH * SEQ * CH];     // [b,t,c]
__device__ __half g_x16 [BATCH * SEQ * CH];      // x
__device__ __half g_wa16[3 * CH * CH];           // w_attn^T: [3072][1024]
__device__ __half g_wp16[CH * CH];               // w_proj^T: [1024][1024]

#define MMA_F16(d, a, b)                                                   \
    asm volatile(                                                          \
        "mma.sync.aligned.m16n8k16.row.col.f32.f16.f16.f32 "               \
        "{%0,%1,%2,%3},{%4,%5,%6,%7},{%8,%9},{%0,%1,%2,%3};"               \
        : "+f"((d)[0]), "+f"((d)[1]), "+f"((d)[2]), "+f"((d)[3])           \
        : "r"((a)[0]), "r"((a)[1]), "r"((a)[2]), "r"((a)[3]),              \
          "r"((b)[0]), "r"((b)[1]))

#define LDM_X4(r, addr)                                                    \
    asm volatile("ldmatrix.sync.aligned.m8n8.x4.shared.b16 "               \
                 "{%0,%1,%2,%3}, [%4];"                                    \
                 : "=r"((r)[0]), "=r"((r)[1]), "=r"((r)[2]), "=r"((r)[3])  \
                 : "r"(addr))

#define CP_ASYNC16(dst_u32, src_ptr)                                       \
    asm volatile("cp.async.cg.shared.global [%0], [%1], 16;"               \
                 :: "r"(dst_u32), "l"(src_ptr))
#define CP_COMMIT() asm volatile("cp.async.commit_group;")
#define CP_WAIT(N)  asm volatile("cp.async.wait_group %0;" :: "n"(N))

#define MBAR_INIT(addr, cnt)                                               \
    asm volatile("mbarrier.init.shared::cta.b64 [%0], %1;"                 \
                 :: "r"(addr), "r"((uint32_t)(cnt)) : "memory")
#define MBAR_ARRIVE(addr)                                                  \
    asm volatile("{\n\t.reg .b64 t;\n\t"                                   \
                 "mbarrier.arrive.shared::cta.b64 t, [%0];\n\t}"           \
                 :: "r"(addr) : "memory")
#define CPA_MBAR_ARRIVE(addr)                                              \
    asm volatile("cp.async.mbarrier.arrive.noinc.shared::cta.b64 [%0];"    \
                 :: "r"(addr) : "memory")

__device__ __forceinline__ void mbar_wait(uint32_t mbar, uint32_t parity) {
    asm volatile(
        "{\n\t.reg .pred P;\n\t"
        "W_%=:\n\t"
        "mbarrier.try_wait.parity.acquire.cta.shared::cta.b64 P, [%0], %1, 0x989680;\n\t"
        "@!P bra W_%=;\n\t"
        "}" :: "r"(mbar), "r"(parity) : "memory");
}

__device__ __forceinline__ uint32_t smem_u32(const void* p) {
    return (uint32_t)__cvta_generic_to_shared(p);
}

// ---------------------------------------------------------------------------
// Prologue converts (fp32 -> fp16)
// ---------------------------------------------------------------------------
__global__ void cvt_x_kernel(const float* __restrict__ src, int n4)
{
    int i = blockIdx.x * blockDim.x + threadIdx.x;
    if (i < n4) {
        float4 v = reinterpret_cast<const float4*>(src)[i];
        __half2 h0 = __floats2half2_rn(v.x, v.y);
        __half2 h1 = __floats2half2_rn(v.z, v.w);
        reinterpret_cast<__half2*>(g_x16)[2 * i]     = h0;
        reinterpret_cast<__half2*>(g_x16)[2 * i + 1] = h1;
    }
}

// Transpose + fp16: src [CH][N] -> dst [N][CH]
__global__ void cvt_T_kernel(const float* __restrict__ src, int sel, int N)
{
    __shared__ float tile[32][33];
    __half* dst = (sel == 1) ? g_wa16 : g_wp16;
    int n0 = blockIdx.x * 32, k0 = blockIdx.y * 32;
    int tx = threadIdx.x, ty = threadIdx.y;  // 32 x 8
#pragma unroll
    for (int i = 0; i < 4; i++)
        tile[ty + 8 * i][tx] = src[(size_t)(k0 + ty + 8 * i) * N + n0 + tx];
    __syncthreads();
#pragma unroll
    for (int i = 0; i < 2; i++) {
        int nl = ty + i * 8 + (tx >> 4) * 16;
        int kc = (tx & 15) * 2;
        __half2 h = __floats2half2_rn(tile[kc][nl], tile[kc + 1][nl]);
        *reinterpret_cast<__half2*>(dst + (size_t)(n0 + nl) * CH + k0 + kc) = h;
    }
}

// ---------------------------------------------------------------------------
// FP16 GEMM core: block 128x128, BK=64, 8 warps (2x4), warp tile 64x32.
// 3-stage ring with mbarrier producer/consumer (warp skew tolerance 1 slab):
//   full[s]  : 256 cp.async arrivals (slab data complete)
//   empty[s] : 8 warp arrivals (all warps done reading the slab)
// ---------------------------------------------------------------------------
#define GP 72                        // smem pitch (halves); 144B rows
#define GROWB (GP * 2)
#define GBUFB (128 * GROWB)          // 18432 B per operand buffer
#define NSTAGE 3
#define GEMM_SMEM (2 * NSTAGE * GBUFB + 64)   // + barriers

__device__ __forceinline__ void gemm_issue_loads(
    const __half* __restrict__ A, const __half* __restrict__ B,
    int m0, int n0, int k0, uint32_t sA, uint32_t sB, int tid)
{
#pragma unroll
    for (int it = 0; it < 4; it++) {
        int idx = it * 256 + tid;
        int row = idx >> 3, c = idx & 7;
        CP_ASYNC16(sA + row * GROWB + c * 16,
                   A + (size_t)(m0 + row) * CH + k0 + c * 8);
    }
#pragma unroll
    for (int it = 0; it < 4; it++) {
        int idx = it * 256 + tid;
        int row = idx >> 3, c = idx & 7;
        CP_ASYNC16(sB + row * GROWB + c * 16,
                   B + (size_t)(n0 + row) * CH + k0 + c * 8);
    }
}

__device__ __forceinline__ void f16_gemm_tile(
    const __half* __restrict__ A, const __half* __restrict__ B,
    int m0, int n0,
    float acc[4][4][4],
    uint32_t sbase, int tid)
{
    const int lane  = tid & 31;
    const int wid   = tid >> 5;
    const int wm    = wid & 1;
    const int wn    = wid >> 1;
    const int l16   = lane & 15;
    const int lane8 = lane & 7;

    const uint32_t sA0 = sbase;
    const uint32_t sB0 = sbase + NSTAGE * GBUFB;
    const uint32_t mbF = sbase + 2 * NSTAGE * GBUFB;   // 3 x 8B full
    const uint32_t mbE = mbF + 24;                     // 3 x 8B empty

    const uint32_t a_lm =
        ((wm * 64 + l16) * GP + (lane >> 4) * 8) * 2;
    const uint32_t b_lm =
        ((wn * 32 + (lane >> 4) * 8 + lane8) * GP +
         ((lane >> 3) & 1) * 8) * 2;

    if (tid == 0) {
#pragma unroll
        for (int i = 0; i < NSTAGE; i++) {
            MBAR_INIT(mbF + i * 8, 256);
            MBAR_INIT(mbE + i * 8, 8);
        }
    }
    __syncthreads();

    // Prologue: slabs 0 (stage 0) and 1 (stage 1) in flight
    gemm_issue_loads(A, B, m0, n0, 0, sA0, sB0, tid);
    CPA_MBAR_ARRIVE(mbF + 0);
    gemm_issue_loads(A, B, m0, n0, 64, sA0 + GBUFB, sB0 + GBUFB, tid);
    CPA_MBAR_ARRIVE(mbF + 8);

    const int nk = CH / 64;   // 16
    int s = 0;  uint32_t fp = 0;    // consume stage + parity
    int s2 = 2;                     // produce stage (slab ki+2)
    int cc = 0; uint32_t ep = 0;    // empty-wait parity tracker

    for (int ki = 0; ki < nk; ki++) {
        mbar_wait(mbF + s * 8, fp);

        const uint32_t Ab = sA0 + s * GBUFB;
        const uint32_t Bb = sB0 + s * GBUFB;

        uint32_t af[2][4][4];
#pragma unroll
        for (int mt = 0; mt < 4; mt++)
            LDM_X4(af[0][mt], Ab + a_lm + mt * 2304);   // ks=0

#pragma unroll
        for (int ks = 0; ks < 4; ks++) {
            const int cur = ks & 1;
            uint32_t bf[2][4];
            LDM_X4(bf[0], Bb + b_lm + ks * 32);
            LDM_X4(bf[1], Bb + b_lm + 2304 + ks * 32);
            if (ks < 3) {
#pragma unroll
                for (int mt = 0; mt < 4; mt++)
                    LDM_X4(af[cur ^ 1][mt],
                           Ab + a_lm + mt * 2304 + (ks + 1) * 32);
            }
#pragma unroll
            for (int mt = 0; mt < 4; mt++) {
#pragma unroll
                for (int nt2 = 0; nt2 < 2; nt2++) {
                    MMA_F16(acc[mt][2 * nt2],     af[cur][mt], &bf[nt2][0]);
                    MMA_F16(acc[mt][2 * nt2 + 1], af[cur][mt], &bf[nt2][2]);
                }
            }
        }

        // Produce slab ki+2 into stage s2 (last used by slab ki-1).
        if (ki + 2 < nk) {
            if (ki >= 1) {
                mbar_wait(mbE + s2 * 8, ep);
                cc++; if (cc == 3) { cc = 0; ep ^= 1; }
            }
            gemm_issue_loads(A, B, m0, n0, (ki + 2) * 64,
                             sA0 + s2 * GBUFB, sB0 + s2 * GBUFB, tid);
            CPA_MBAR_ARRIVE(mbF + s2 * 8);
        }

        __syncwarp();
        if (lane == 0) MBAR_ARRIVE(mbE + s * 8);   // this warp done with slab ki

        s = (s + 1 == NSTAGE) ? 0 : s + 1;
        if (s == 0) fp ^= 1;
        s2 = (s2 + 1 == NSTAGE) ? 0 : s2 + 1;
    }
}

// ---------------------------------------------------------------------------
// Kernel 1: QKV GEMM. q/k direct half2 stores [b,h,t,d]; v staged through
// smem (transposed) then coalesced 16B stores into [b,h,d,t].
// q carries folded softmax*log2e scale.
// ---------------------------------------------------------------------------
#define VPS 144   // v-staging pitch (halves)

__global__ __launch_bounds__(256, 2) void qkv_gemm_kernel(
    const float* __restrict__ bias)
{
    extern __shared__ float smg[];
    const uint32_t sbase = smem_u32(smg);
    const int tid = threadIdx.x;
    const int m0 = blockIdx.y * 128;
    const int n0 = blockIdx.x * 128;

    float acc[4][4][4];
#pragma unroll
    for (int i = 0; i < 4; i++)
#pragma unroll
        for (int j = 0; j < 4; j++)
#pragma unroll
            for (int q = 0; q < 4; q++) acc[i][j][q] = 0.f;

    f16_gemm_tile(g_x16, g_wa16, m0, n0, acc, sbase, tid);
    __syncthreads();   // smem free for v staging

    const int lane = tid & 31;
    const int wid  = tid >> 5;
    const int wm   = wid & 1;
    const int wn   = wid >> 1;
    const int lr   = lane >> 2;
    const int lc   = lane & 3;

    const int sec = n0 >> 10;  // 0=q 1=k 2=v
    const float scale = (sec == 0) ? 0.125f * LOG2E : 1.0f;
    const int bb = m0 >> 11;
    const int t0 = m0 & (SEQ - 1);

    if (sec < 2) {
        __half* dst = (sec == 0) ? g_q16 : g_k16;
#pragma unroll
        for (int mt = 0; mt < 4; mt++) {
            int t = t0 + wm * 64 + mt * 16 + lr;
#pragma unroll
            for (int nt = 0; nt < 4; nt++) {
                int c0 = n0 + wn * 32 + nt * 8 + lc * 2;
                float b0 = bias[c0], b1 = bias[c0 + 1];
                int n1 = c0 & (CH - 1);
                int h  = n1 >> 6;
                int d  = n1 & 63;
                __half* p = dst + ((size_t)((bb * NHEAD + h) * SEQ + t)) * HDIM + d;
                *reinterpret_cast<__half2*>(p) =
                    __floats2half2_rn((acc[mt][nt][0] + b0) * scale,
                                      (acc[mt][nt][1] + b1) * scale);
                *reinterpret_cast<__half2*>(p + 8 * HDIM) =
                    __floats2half2_rn((acc[mt][nt][2] + b0) * scale,
                                      (acc[mt][nt][3] + b1) * scale);
            }
        }
    } else {
        // v: stage transposed [c][VPS] halves, then coalesced t-runs
        __half* smh = reinterpret_cast<__half*>(smg);
#pragma unroll
        for (int mt = 0; mt < 4; mt++) {
            int rm = wm * 64 + mt * 16 + lr;
#pragma unroll
            for (int nt = 0; nt < 4; nt++) {
                int cc = wn * 32 + nt * 8 + lc * 2;
                float b0 = bias[n0 + cc], b1 = bias[n0 + cc + 1];
                smh[cc * VPS + rm]           = __float2half_rn(acc[mt][nt][0] + b0);
                smh[(cc + 1) * VPS + rm]     = __float2half_rn(acc[mt][nt][1] + b1);
                smh[cc * VPS + rm + 8]       = __float2half_rn(acc[mt][nt][2] + b0);
                smh[(cc + 1) * VPS + rm + 8] = __float2half_rn(acc[mt][nt][3] + b1);
            }
        }
        __syncthreads();
        const int l16 = lane & 15;
#pragma unroll
        for (int it = 0; it < 8; it++) {
            int c = wid * 16 + it * 2 + (lane >> 4);
            uint4 val = *reinterpret_cast<uint4*>(&smh[c * VPS + l16 * 8]);
            int n1 = (n0 + c) & (CH - 1);
            int h = n1 >> 6, d = n1 & 63;
            __half* p = g_v16 +
                ((size_t)((bb * NHEAD + h) * HDIM + d)) * SEQ + t0 + l16 * 8;
            *reinterpret_cast<uint4*>(p) = val;
        }
    }
}

// ---------------------------------------------------------------------------
// Kernel 3: output projection (fp32 out, direct float2 stores)
// ---------------------------------------------------------------------------
__global__ __launch_bounds__(256, 2) void proj_gemm_kernel(
    const float* __restrict__ bias, float* __restrict__ out)
{
    extern __shared__ float smg[];
    const uint32_t sbase = smem_u32(smg);
    const int tid = threadIdx.x;
    const int m0 = blockIdx.y * 128;
    const int n0 = blockIdx.x * 128;

    float acc[4][4][4];
#pragma unroll
    for (int i = 0; i < 4; i++)
#pragma unroll
        for (int j = 0; j < 4; j++)
#pragma unroll
            for (int q = 0; q < 4; q++) acc[i][j][q] = 0.f;

    f16_gemm_tile(g_att16, g_wp16, m0, n0, acc, sbase, tid);

    const int lane = tid & 31;
    const int wid  = tid >> 5;
    const int wm   = wid & 1;
    const int wn   = wid >> 1;
    const int lr   = lane >> 2;
    const int lc   = lane & 3;

#pragma unroll
    for (int mt = 0; mt < 4; mt++) {
        int r0 = m0 + wm * 64 + mt * 16 + lr;
#pragma unroll
        for (int nt = 0; nt < 4; nt++) {
            int c0 = n0 + wn * 32 + nt * 8 + lc * 2;
            float b0 = bias[c0], b1 = bias[c0 + 1];
            *reinterpret_cast<float2*>(&out[(size_t)r0 * CH + c0]) =
                make_float2(acc[mt][nt][0] + b0, acc[mt][nt][1] + b1);
            *reinterpret_cast<float2*>(&out[(size_t)(r0 + 8) * CH + c0]) =
                make_float2(acc[mt][nt][2] + b0, acc[mt][nt][3] + b1);
        }
    }
}

// ---------------------------------------------------------------------------
// Kernel 2: causal flash attention, fp16 mma m16n8k16, mbarrier pipeline
// (round-12 proven), exp2 softmax (log2e folded into q).
// ---------------------------------------------------------------------------
#define AP 72
#define AROWB (AP * 2)
#define QBUFB (128 * AROWB)
#define KVBUFB (64 * AROWB)
#define ATTN_SMEM (QBUFB + 4 * KVBUFB + 32)

__device__ __forceinline__ void attn_issue_kv(
    const __half* __restrict__ kp, const __half* __restrict__ vp,
    int k0, uint32_t sK, uint32_t sV, int tid)
{
#pragma unroll
    for (int it = 0; it < 2; it++) {
        int idx = it * 256 + tid;
        int row = idx >> 3;
        int c   = idx & 7;
        CP_ASYNC16(sK + row * AROWB + c * 16,
                   kp + (size_t)(k0 + row) * HDIM + c * 8);
        CP_ASYNC16(sV + row * AROWB + c * 16,
                   vp + (size_t)row * SEQ + k0 + c * 8);
    }
}

__global__ __launch_bounds__(256, 2) void attn_kernel()
{
    extern __shared__ float sm[];
    const uint32_t sbase = smem_u32(sm);
    const uint32_t sQs = sbase;
    const uint32_t sKs = sbase + QBUFB;
    const uint32_t sVs = sKs + 2 * KVBUFB;
    const uint32_t mbF = sVs + 2 * KVBUFB;
    const uint32_t mbE = mbF + 16;

    const int tid   = threadIdx.x;
    const int lane  = tid & 31;
    const int wq    = tid >> 5;
    const int lr    = lane >> 2;
    const int lc    = lane & 3;
    const int l16   = lane & 15;
    const int lane8 = lane & 7;

    const int qt = (int)gridDim.x - 1 - (int)blockIdx.x;  // big tiles first
    const int bh = blockIdx.y;
    const int q0 = qt * 128;

    const __half* qp = g_q16 + (size_t)bh * SEQ * HDIM;
    const __half* kp = g_k16 + (size_t)bh * SEQ * HDIM;
    const __half* vp = g_v16 + (size_t)bh * HDIM * SEQ;

    const uint32_t q_lm = sQs +
        ((wq * 16 + l16) * AP + (lane >> 4) * 8) * 2;
    const uint32_t kv_lm =
        (((lane >> 4) * 8 + lane8) * AP + ((lane >> 3) & 1) * 8) * 2;
    const uint32_t p_lm = (l16 * AP + (lane >> 4) * 8) * 2;

    if (tid == 0) {
        MBAR_INIT(mbF + 0, 256);
        MBAR_INIT(mbF + 8, 256);
        MBAR_INIT(mbE + 0, 8);
        MBAR_INIT(mbE + 8, 8);
    }
    __syncthreads();

#pragma unroll
    for (int it = 0; it < 4; it++) {
        int idx = it * 256 + tid;
        int row = idx >> 3;
        int c   = idx & 7;
        CP_ASYNC16(sQs + row * AROWB + c * 16,
                   qp + (size_t)(q0 + row) * HDIM + c * 8);
    }
    attn_issue_kv(kp, vp, 0, sKs, sVs, tid);
    CPA_MBAR_ARRIVE(mbF + 0);
    attn_issue_kv(kp, vp, 64, sKs + KVBUFB, sVs + KVBUFB, tid);
    CPA_MBAR_ARRIVE(mbF + 8);

    uint32_t qf[4][4];
    const uint32_t sPt = sQs + wq * 16 * AROWB;
    __half* Pt = reinterpret_cast<__half*>(sm) + wq * 16 * AP;

    float o[8][4] = {};
    float m0v = -1e30f, m1v = -1e30f;
    float l0v = 0.f, l1v = 0.f;

    const int nkt  = 2 * qt + 2;
    const int r_hi = q0 + wq * 16 + 15;

    for (int kt = 0; kt < nkt; kt++) {
        const int k0 = kt * 64;
        const uint32_t s  = (uint32_t)(kt & 1);
        const uint32_t cp = (uint32_t)((kt >> 1) & 1);

        if (kt >= 1 && kt + 1 < nkt) {
            const uint32_t so = s ^ 1u;
            mbar_wait(mbE + so * 8, (uint32_t)(((kt - 1) >> 1) & 1));
            attn_issue_kv(kp, vp, (kt + 1) * 64,
                          sKs + so * KVBUFB, sVs + so * KVBUFB, tid);
            CPA_MBAR_ARRIVE(mbF + so * 8);
        }

        mbar_wait(mbF + s * 8, cp);

        if (kt == 0) {
#pragma unroll
            for (int ks = 0; ks < 4; ks++)
                LDM_X4(qf[ks], q_lm + ks * 32);
        }

        if (k0 <= r_hi) {
            const uint32_t Kb = sKs + s * KVBUFB;
            const uint32_t Vb = sVs + s * KVBUFB;

            float sacc[8][4];
#pragma unroll
            for (int nt = 0; nt < 8; nt++)
#pragma unroll
                for (int q = 0; q < 4; q++) sacc[nt][q] = 0.f;

#pragma unroll
            for (int ks = 0; ks < 4; ks++) {
#pragma unroll
                for (int nt2 = 0; nt2 < 4; nt2++) {
                    uint32_t bf[4];
                    LDM_X4(bf, Kb + kv_lm + nt2 * 2304 + ks * 32);
                    MMA_F16(sacc[2 * nt2],     qf[ks], &bf[0]);
                    MMA_F16(sacc[2 * nt2 + 1], qf[ks], &bf[2]);
                }
            }

            if (kt >= 2 * qt) {
                int r0g = q0 + wq * 16 + lr;
#pragma unroll
                for (int nt = 0; nt < 8; nt++) {
                    int c0g = k0 + nt * 8 + 2 * lc;
                    if (c0g     > r0g)     sacc[nt][0] = -1e30f;
                    if (c0g + 1 > r0g)     sacc[nt][1] = -1e30f;
                    if (c0g     > r0g + 8) sacc[nt][2] = -1e30f;
                    if (c0g + 1 > r0g + 8) sacc[nt][3] = -1e30f;
                }
            }

            float rm0 = -1e30f, rm1 = -1e30f;
#pragma unroll
            for (int nt = 0; nt < 8; nt++) {
                rm0 = fmaxf(rm0, fmaxf(sacc[nt][0], sacc[nt][1]));
                rm1 = fmaxf(rm1, fmaxf(sacc[nt][2], sacc[nt][3]));
            }
            rm0 = fmaxf(rm0, __shfl_xor_sync(0xffffffffu, rm0, 1));
            rm0 = fmaxf(rm0, __shfl_xor_sync(0xffffffffu, rm0, 2));
            rm1 = fmaxf(rm1, __shfl_xor_sync(0xffffffffu, rm1, 1));
            rm1 = fmaxf(rm1, __shfl_xor_sync(0xffffffffu, rm1, 2));

            float mn0 = fmaxf(m0v, rm0);
            float mn1 = fmaxf(m1v, rm1);
            float cr0 = exp2f(m0v - mn0);
            float cr1 = exp2f(m1v - mn1);
            m0v = mn0; m1v = mn1;

            float rs0 = 0.f, rs1 = 0.f;
#pragma unroll
            for (int nt = 0; nt < 8; nt++) {
                sacc[nt][0] = exp2f(sacc[nt][0] - mn0);
                sacc[nt][1] = exp2f(sacc[nt][1] - mn0);
                sacc[nt][2] = exp2f(sacc[nt][2] - mn1);
                sacc[nt][3] = exp2f(sacc[nt][3] - mn1);
                rs0 += sacc[nt][0] + sacc[nt][1];
                rs1 += sacc[nt][2] + sacc[nt][3];
            }
            rs0 += __shfl_xor_sync(0xffffffffu, rs0, 1);
            rs0 += __shfl_xor_sync(0xffffffffu, rs0, 2);
            rs1 += __shfl_xor_sync(0xffffffffu, rs1, 1);
            rs1 += __shfl_xor_sync(0xffffffffu, rs1, 2);
            l0v = l0v * cr0 + rs0;
            l1v = l1v * cr1 + rs1;
#pragma unroll
            for (int nt = 0; nt < 8; nt++) {
                o[nt][0] *= cr0; o[nt][1] *= cr0;
                o[nt][2] *= cr1; o[nt][3] *= cr1;
            }

#pragma unroll
            for (int nt = 0; nt < 8; nt++) {
                *reinterpret_cast<__half2*>(&Pt[lr * AP + nt * 8 + 2 * lc]) =
                    __floats2half2_rn(sacc[nt][0], sacc[nt][1]);
                *reinterpret_cast<__half2*>(&Pt[(lr + 8) * AP + nt * 8 + 2 * lc]) =
                    __floats2half2_rn(sacc[nt][2], sacc[nt][3]);
            }
            __syncwarp();

#pragma unroll
            for (int ks = 0; ks < 4; ks++) {
                uint32_t a[4];
                LDM_X4(a, sPt + p_lm + ks * 32);
#pragma unroll
                for (int nt2 = 0; nt2 < 4; nt2++) {
                    uint32_t b[4];
                    LDM_X4(b, Vb + kv_lm + nt2 * 2304 + ks * 32);
                    MMA_F16(o[2 * nt2],     a, &b[0]);
                    MMA_F16(o[2 * nt2 + 1], a, &b[2]);
                }
            }
        }

        __syncwarp();
        if (lane == 0) MBAR_ARRIVE(mbE + s * 8);
    }

    const int b = bh >> 4, h = bh & 15;
    const int r0g = q0 + wq * 16 + lr;
    const float inv0 = 1.0f / l0v;
    const float inv1 = 1.0f / l1v;
#pragma unroll
    for (int nt = 0; nt < 8; nt++) {
        int cg = h * 64 + nt * 8 + 2 * lc;
        *reinterpret_cast<__half2*>(
            &g_att16[(size_t)(b * SEQ + r0g) * CH + cg]) =
            __floats2half2_rn(o[nt][0] * inv0, o[nt][1] * inv0);
        *reinterpret_cast<__half2*>(
            &g_att16[(size_t)(b * SEQ + r0g + 8) * CH + cg]) =
            __floats2half2_rn(o[nt][2] * inv1, o[nt][3] * inv1);
    }
}

// ---------------------------------------------------------------------------
extern "C" void kernel_launch(void* const* d_in, const int* in_sizes, int n_in,
                              void* d_out, int out_size)
{
    const float* x      = (const float*)d_in[0];
    const float* w_attn = (const float*)d_in[1];
    const float* b_attn = (const float*)d_in[2];
    const float* w_proj = (const float*)d_in[3];
    const float* b_proj = (const float*)d_in[4];
    float* out = (float*)d_out;

    cudaFuncSetAttribute(qkv_gemm_kernel,
                         cudaFuncAttributeMaxDynamicSharedMemorySize, GEMM_SMEM);
    cudaFuncSetAttribute(proj_gemm_kernel,
                         cudaFuncAttributeMaxDynamicSharedMemorySize, GEMM_SMEM);
    cudaFuncSetAttribute(attn_kernel,
                         cudaFuncAttributeMaxDynamicSharedMemorySize, ATTN_SMEM);

    // 0) fp16-convert x; transpose+convert weights to [N][K]
    cvt_x_kernel<<<(BATCH * SEQ * CH / 4 + 255) / 256, 256>>>(x,
        BATCH * SEQ * CH / 4);
    cvt_T_kernel<<<dim3(3 * CH / 32, CH / 32), dim3(32, 8)>>>(w_attn, 1, 3 * CH);
    cvt_T_kernel<<<dim3(CH / 32, CH / 32), dim3(32, 8)>>>(w_proj, 2, CH);

    // 1) QKV GEMM: grid (3072/128, 8192/128)
    qkv_gemm_kernel<<<dim3(24, 64), 256, GEMM_SMEM>>>(b_attn);

    // 2) Attention: grid (16 q-tiles, B*NH)
    attn_kernel<<<dim3(16, BATCH * NHEAD), 256, ATTN_SMEM>>>();

    // 3) Projection: grid (1024/128, 8192/128)
    proj_gemm_kernel<<<dim3(8, 64), 256, GEMM_SMEM>>>(b_proj, out);
}

// round 14
// speedup vs baseline: 2.0172x; 1.0298x over previous
#include <cuda_runtime.h>
#include <cuda_fp16.h>
#include <cstdint>

#define BATCH 4
#define SEQ   2048
#define CH    1024
#define NHEAD 16
#define HDIM  64
#define LOG2E 1.4426950408889634f

// Scratch (allocation-free rule: __device__ globals). All operands fp16.
// q,k: [b,h,t,d]; v: [b,h,d,t] (transposed for PV ldmatrix).
__device__ __half g_q16[BATCH * NHEAD * SEQ * HDIM];
__device__ __half g_k16[BATCH * NHEAD * SEQ * HDIM];
__device__ __half g_v16[BATCH * NHEAD * HDIM * SEQ];
__device__ __half g_att16[BATCH * SEQ * CH];     // [b,t,c]
__device__ __half g_x16 [BATCH * SEQ * CH];      // x
__device__ __half g_wa16[3 * CH * CH];           // w_attn^T: [3072][1024]
__device__ __half g_wp16[CH * CH];               // w_proj^T: [1024][1024]

#define MMA_F16(d, a, b)                                                   \
    asm volatile(                                                          \
        "mma.sync.aligned.m16n8k16.row.col.f32.f16.f16.f32 "               \
        "{%0,%1,%2,%3},{%4,%5,%6,%7},{%8,%9},{%0,%1,%2,%3};"               \
        : "+f"((d)[0]), "+f"((d)[1]), "+f"((d)[2]), "+f"((d)[3])           \
        : "r"((a)[0]), "r"((a)[1]), "r"((a)[2]), "r"((a)[3]),              \
          "r"((b)[0]), "r"((b)[1]))

#define LDM_X4(r, addr)                                                    \
    asm volatile("ldmatrix.sync.aligned.m8n8.x4.shared.b16 "               \
                 "{%0,%1,%2,%3}, [%4];"                                    \
                 : "=r"((r)[0]), "=r"((r)[1]), "=r"((r)[2]), "=r"((r)[3])  \
                 : "r"(addr))

#define CP_ASYNC16(dst_u32, src_ptr)                                       \
    asm volatile("cp.async.cg.shared.global [%0], [%1], 16;"               \
                 :: "r"(dst_u32), "l"(src_ptr))
#define CP_COMMIT() asm volatile("cp.async.commit_group;")
#define CP_WAIT(N)  asm volatile("cp.async.wait_group %0;" :: "n"(N))

#define MBAR_INIT(addr, cnt)                                               \
    asm volatile("mbarrier.init.shared::cta.b64 [%0], %1;"                 \
                 :: "r"(addr), "r"((uint32_t)(cnt)) : "memory")
#define MBAR_ARRIVE(addr)                                                  \
    asm volatile("{\n\t.reg .b64 t;\n\t"                                   \
                 "mbarrier.arrive.shared::cta.b64 t, [%0];\n\t}"           \
                 :: "r"(addr) : "memory")
#define CPA_MBAR_ARRIVE(addr)                                              \
    asm volatile("cp.async.mbarrier.arrive.noinc.shared::cta.b64 [%0];"    \
                 :: "r"(addr) : "memory")

__device__ __forceinline__ void mbar_wait(uint32_t mbar, uint32_t parity) {
    asm volatile(
        "{\n\t.reg .pred P;\n\t"
        "W_%=:\n\t"
        "mbarrier.try_wait.parity.acquire.cta.shared::cta.b64 P, [%0], %1, 0x989680;\n\t"
        "@!P bra W_%=;\n\t"
        "}" :: "r"(mbar), "r"(parity) : "memory");
}

__device__ __forceinline__ uint32_t smem_u32(const void* p) {
    return (uint32_t)__cvta_generic_to_shared(p);
}

__device__ __forceinline__ uint32_t packh2(float a, float b) {
    __half2 h = __floats2half2_rn(a, b);
    return *reinterpret_cast<uint32_t*>(&h);
}

// ---------------------------------------------------------------------------
// Prologue converts (fp32 -> fp16)
// ---------------------------------------------------------------------------
__global__ void cvt_x_kernel(const float* __restrict__ src, int n4)
{
    int i = blockIdx.x * blockDim.x + threadIdx.x;
    if (i < n4) {
        float4 v = reinterpret_cast<const float4*>(src)[i];
        __half2 h0 = __floats2half2_rn(v.x, v.y);
        __half2 h1 = __floats2half2_rn(v.z, v.w);
        reinterpret_cast<__half2*>(g_x16)[2 * i]     = h0;
        reinterpret_cast<__half2*>(g_x16)[2 * i + 1] = h1;
    }
}

// Transpose + fp16: src [CH][N] -> dst [N][CH]
__global__ void cvt_T_kernel(const float* __restrict__ src, int sel, int N)
{
    __shared__ float tile[32][33];
    __half* dst = (sel == 1) ? g_wa16 : g_wp16;
    int n0 = blockIdx.x * 32, k0 = blockIdx.y * 32;
    int tx = threadIdx.x, ty = threadIdx.y;  // 32 x 8
#pragma unroll
    for (int i = 0; i < 4; i++)
        tile[ty + 8 * i][tx] = src[(size_t)(k0 + ty + 8 * i) * N + n0 + tx];
    __syncthreads();
#pragma unroll
    for (int i = 0; i < 2; i++) {
        int nl = ty + i * 8 + (tx >> 4) * 16;
        int kc = (tx & 15) * 2;
        __half2 h = __floats2half2_rn(tile[kc][nl], tile[kc + 1][nl]);
        *reinterpret_cast<__half2*>(dst + (size_t)(n0 + nl) * CH + k0 + kc) = h;
    }
}

// ---------------------------------------------------------------------------
// FP16 GEMM core (round-13 proven): block 128x128, BK=64, 8 warps (2x4),
// 3-stage mbarrier producer/consumer ring + register double-buffered A frags.
// ---------------------------------------------------------------------------
#define GP 72
#define GROWB (GP * 2)
#define GBUFB (128 * GROWB)
#define NSTAGE 3
#define GEMM_SMEM (2 * NSTAGE * GBUFB + 64)

__device__ __forceinline__ void gemm_issue_loads(
    const __half* __restrict__ A, const __half* __restrict__ B,
    int m0, int n0, int k0, uint32_t sA, uint32_t sB, int tid)
{
#pragma unroll
    for (int it = 0; it < 4; it++) {
        int idx = it * 256 + tid;
        int row = idx >> 3, c = idx & 7;
        CP_ASYNC16(sA + row * GROWB + c * 16,
                   A + (size_t)(m0 + row) * CH + k0 + c * 8);
    }
#pragma unroll
    for (int it = 0; it < 4; it++) {
        int idx = it * 256 + tid;
        int row = idx >> 3, c = idx & 7;
        CP_ASYNC16(sB + row * GROWB + c * 16,
                   B + (size_t)(n0 + row) * CH + k0 + c * 8);
    }
}

__device__ __forceinline__ void f16_gemm_tile(
    const __half* __restrict__ A, const __half* __restrict__ B,
    int m0, int n0,
    float acc[4][4][4],
    uint32_t sbase, int tid)
{
    const int lane  = tid & 31;
    const int wid   = tid >> 5;
    const int wm    = wid & 1;
    const int wn    = wid >> 1;
    const int l16   = lane & 15;
    const int lane8 = lane & 7;

    const uint32_t sA0 = sbase;
    const uint32_t sB0 = sbase + NSTAGE * GBUFB;
    const uint32_t mbF = sbase + 2 * NSTAGE * GBUFB;
    const uint32_t mbE = mbF + 24;

    const uint32_t a_lm =
        ((wm * 64 + l16) * GP + (lane >> 4) * 8) * 2;
    const uint32_t b_lm =
        ((wn * 32 + (lane >> 4) * 8 + lane8) * GP +
         ((lane >> 3) & 1) * 8) * 2;

    if (tid == 0) {
#pragma unroll
        for (int i = 0; i < NSTAGE; i++) {
            MBAR_INIT(mbF + i * 8, 256);
            MBAR_INIT(mbE + i * 8, 8);
        }
    }
    __syncthreads();

    gemm_issue_loads(A, B, m0, n0, 0, sA0, sB0, tid);
    CPA_MBAR_ARRIVE(mbF + 0);
    gemm_issue_loads(A, B, m0, n0, 64, sA0 + GBUFB, sB0 + GBUFB, tid);
    CPA_MBAR_ARRIVE(mbF + 8);

    const int nk = CH / 64;   // 16
    int s = 0;  uint32_t fp = 0;
    int s2 = 2;
    int cc = 0; uint32_t ep = 0;

    for (int ki = 0; ki < nk; ki++) {
        mbar_wait(mbF + s * 8, fp);

        const uint32_t Ab = sA0 + s * GBUFB;
        const uint32_t Bb = sB0 + s * GBUFB;

        uint32_t af[2][4][4];
#pragma unroll
        for (int mt = 0; mt < 4; mt++)
            LDM_X4(af[0][mt], Ab + a_lm + mt * 2304);

#pragma unroll
        for (int ks = 0; ks < 4; ks++) {
            const int cur = ks & 1;
            uint32_t bf[2][4];
            LDM_X4(bf[0], Bb + b_lm + ks * 32);
            LDM_X4(bf[1], Bb + b_lm + 2304 + ks * 32);
            if (ks < 3) {
#pragma unroll
                for (int mt = 0; mt < 4; mt++)
                    LDM_X4(af[cur ^ 1][mt],
                           Ab + a_lm + mt * 2304 + (ks + 1) * 32);
            }
#pragma unroll
            for (int mt = 0; mt < 4; mt++) {
#pragma unroll
                for (int nt2 = 0; nt2 < 2; nt2++) {
                    MMA_F16(acc[mt][2 * nt2],     af[cur][mt], &bf[nt2][0]);
                    MMA_F16(acc[mt][2 * nt2 + 1], af[cur][mt], &bf[nt2][2]);
                }
            }
        }

        if (ki + 2 < nk) {
            if (ki >= 1) {
                mbar_wait(mbE + s2 * 8, ep);
                cc++; if (cc == 3) { cc = 0; ep ^= 1; }
            }
            gemm_issue_loads(A, B, m0, n0, (ki + 2) * 64,
                             sA0 + s2 * GBUFB, sB0 + s2 * GBUFB, tid);
            CPA_MBAR_ARRIVE(mbF + s2 * 8);
        }

        __syncwarp();
        if (lane == 0) MBAR_ARRIVE(mbE + s * 8);

        s = (s + 1 == NSTAGE) ? 0 : s + 1;
        if (s == 0) fp ^= 1;
        s2 = (s2 + 1 == NSTAGE) ? 0 : s2 + 1;
    }
}

// ---------------------------------------------------------------------------
// Kernel 1: QKV GEMM (round-13 proven epilogues).
// ---------------------------------------------------------------------------
#define VPS 144

__global__ __launch_bounds__(256, 2) void qkv_gemm_kernel(
    const float* __restrict__ bias)
{
    extern __shared__ float smg[];
    const uint32_t sbase = smem_u32(smg);
    const int tid = threadIdx.x;
    const int m0 = blockIdx.y * 128;
    const int n0 = blockIdx.x * 128;

    float acc[4][4][4];
#pragma unroll
    for (int i = 0; i < 4; i++)
#pragma unroll
        for (int j = 0; j < 4; j++)
#pragma unroll
            for (int q = 0; q < 4; q++) acc[i][j][q] = 0.f;

    f16_gemm_tile(g_x16, g_wa16, m0, n0, acc, sbase, tid);
    __syncthreads();

    const int lane = tid & 31;
    const int wid  = tid >> 5;
    const int wm   = wid & 1;
    const int wn   = wid >> 1;
    const int lr   = lane >> 2;
    const int lc   = lane & 3;

    const int sec = n0 >> 10;
    const float scale = (sec == 0) ? 0.125f * LOG2E : 1.0f;
    const int bb = m0 >> 11;
    const int t0 = m0 & (SEQ - 1);

    if (sec < 2) {
        __half* dst = (sec == 0) ? g_q16 : g_k16;
#pragma unroll
        for (int mt = 0; mt < 4; mt++) {
            int t = t0 + wm * 64 + mt * 16 + lr;
#pragma unroll
            for (int nt = 0; nt < 4; nt++) {
                int c0 = n0 + wn * 32 + nt * 8 + lc * 2;
                float b0 = bias[c0], b1 = bias[c0 + 1];
                int n1 = c0 & (CH - 1);
                int h  = n1 >> 6;
                int d  = n1 & 63;
                __half* p = dst + ((size_t)((bb * NHEAD + h) * SEQ + t)) * HDIM + d;
                *reinterpret_cast<__half2*>(p) =
                    __floats2half2_rn((acc[mt][nt][0] + b0) * scale,
                                      (acc[mt][nt][1] + b1) * scale);
                *reinterpret_cast<__half2*>(p + 8 * HDIM) =
                    __floats2half2_rn((acc[mt][nt][2] + b0) * scale,
                                      (acc[mt][nt][3] + b1) * scale);
            }
        }
    } else {
        __half* smh = reinterpret_cast<__half*>(smg);
#pragma unroll
        for (int mt = 0; mt < 4; mt++) {
            int rm = wm * 64 + mt * 16 + lr;
#pragma unroll
            for (int nt = 0; nt < 4; nt++) {
                int cc = wn * 32 + nt * 8 + lc * 2;
                float b0 = bias[n0 + cc], b1 = bias[n0 + cc + 1];
                smh[cc * VPS + rm]           = __float2half_rn(acc[mt][nt][0] + b0);
                smh[(cc + 1) * VPS + rm]     = __float2half_rn(acc[mt][nt][1] + b1);
                smh[cc * VPS + rm + 8]       = __float2half_rn(acc[mt][nt][2] + b0);
                smh[(cc + 1) * VPS + rm + 8] = __float2half_rn(acc[mt][nt][3] + b1);
            }
        }
        __syncthreads();
        const int l16 = lane & 15;
#pragma unroll
        for (int it = 0; it < 8; it++) {
            int c = wid * 16 + it * 2 + (lane >> 4);
            uint4 val = *reinterpret_cast<uint4*>(&smh[c * VPS + l16 * 8]);
            int n1 = (n0 + c) & (CH - 1);
            int h = n1 >> 6, d = n1 & 63;
            __half* p = g_v16 +
                ((size_t)((bb * NHEAD + h) * HDIM + d)) * SEQ + t0 + l16 * 8;
            *reinterpret_cast<uint4*>(p) = val;
        }
    }
}

// ---------------------------------------------------------------------------
// Kernel 3: output projection
// ---------------------------------------------------------------------------
__global__ __launch_bounds__(256, 2) void proj_gemm_kernel(
    const float* __restrict__ bias, float* __restrict__ out)
{
    extern __shared__ float smg[];
    const uint32_t sbase = smem_u32(smg);
    const int tid = threadIdx.x;
    const int m0 = blockIdx.y * 128;
    const int n0 = blockIdx.x * 128;

    float acc[4][4][4];
#pragma unroll
    for (int i = 0; i < 4; i++)
#pragma unroll
        for (int j = 0; j < 4; j++)
#pragma unroll
            for (int q = 0; q < 4; q++) acc[i][j][q] = 0.f;

    f16_gemm_tile(g_att16, g_wp16, m0, n0, acc, sbase, tid);

    const int lane = tid & 31;
    const int wid  = tid >> 5;
    const int wm   = wid & 1;
    const int wn   = wid >> 1;
    const int lr   = lane >> 2;
    const int lc   = lane & 3;

#pragma unroll
    for (int mt = 0; mt < 4; mt++) {
        int r0 = m0 + wm * 64 + mt * 16 + lr;
#pragma unroll
        for (int nt = 0; nt < 4; nt++) {
            int c0 = n0 + wn * 32 + nt * 8 + lc * 2;
            float b0 = bias[c0], b1 = bias[c0 + 1];
            *reinterpret_cast<float2*>(&out[(size_t)r0 * CH + c0]) =
                make_float2(acc[mt][nt][0] + b0, acc[mt][nt][1] + b1);
            *reinterpret_cast<float2*>(&out[(size_t)(r0 + 8) * CH + c0]) =
                make_float2(acc[mt][nt][2] + b0, acc[mt][nt][3] + b1);
        }
    }
}

// ---------------------------------------------------------------------------
// Kernel 2: causal flash attention, fp16 mma m16n8k16, mbarrier pipeline,
// exp2 softmax. NEW: P passes from S accumulators to PV A-fragments via
// in-register half2 repack (m16n8k16 A-frag == two consecutive m16n8
// accumulator frags) — no smem round trip.
// ---------------------------------------------------------------------------
#define AP 72
#define AROWB (AP * 2)
#define QBUFB (128 * AROWB)
#define KVBUFB (64 * AROWB)
#define ATTN_SMEM (QBUFB + 4 * KVBUFB + 32)

__device__ __forceinline__ void attn_issue_kv(
    const __half* __restrict__ kp, const __half* __restrict__ vp,
    int k0, uint32_t sK, uint32_t sV, int tid)
{
#pragma unroll
    for (int it = 0; it < 2; it++) {
        int idx = it * 256 + tid;
        int row = idx >> 3;
        int c   = idx & 7;
        CP_ASYNC16(sK + row * AROWB + c * 16,
                   kp + (size_t)(k0 + row) * HDIM + c * 8);
        CP_ASYNC16(sV + row * AROWB + c * 16,
                   vp + (size_t)row * SEQ + k0 + c * 8);
    }
}

__global__ __launch_bounds__(256, 2) void attn_kernel()
{
    extern __shared__ float sm[];
    const uint32_t sbase = smem_u32(sm);
    const uint32_t sQs = sbase;
    const uint32_t sKs = sbase + QBUFB;
    const uint32_t sVs = sKs + 2 * KVBUFB;
    const uint32_t mbF = sVs + 2 * KVBUFB;
    const uint32_t mbE = mbF + 16;

    const int tid   = threadIdx.x;
    const int lane  = tid & 31;
    const int wq    = tid >> 5;
    const int lr    = lane >> 2;
    const int lc    = lane & 3;
    const int l16   = lane & 15;
    const int lane8 = lane & 7;

    const int qt = (int)gridDim.x - 1 - (int)blockIdx.x;  // big tiles first
    const int bh = blockIdx.y;
    const int q0 = qt * 128;

    const __half* qp = g_q16 + (size_t)bh * SEQ * HDIM;
    const __half* kp = g_k16 + (size_t)bh * SEQ * HDIM;
    const __half* vp = g_v16 + (size_t)bh * HDIM * SEQ;

    const uint32_t q_lm = sQs +
        ((wq * 16 + l16) * AP + (lane >> 4) * 8) * 2;
    const uint32_t kv_lm =
        (((lane >> 4) * 8 + lane8) * AP + ((lane >> 3) & 1) * 8) * 2;

    if (tid == 0) {
        MBAR_INIT(mbF + 0, 256);
        MBAR_INIT(mbF + 8, 256);
        MBAR_INIT(mbE + 0, 8);
        MBAR_INIT(mbE + 8, 8);
    }
    __syncthreads();

#pragma unroll
    for (int it = 0; it < 4; it++) {
        int idx = it * 256 + tid;
        int row = idx >> 3;
        int c   = idx & 7;
        CP_ASYNC16(sQs + row * AROWB + c * 16,
                   qp + (size_t)(q0 + row) * HDIM + c * 8);
    }
    attn_issue_kv(kp, vp, 0, sKs, sVs, tid);
    CPA_MBAR_ARRIVE(mbF + 0);
    attn_issue_kv(kp, vp, 64, sKs + KVBUFB, sVs + KVBUFB, tid);
    CPA_MBAR_ARRIVE(mbF + 8);

    uint32_t qf[4][4];

    float o[8][4] = {};
    float m0v = -1e30f, m1v = -1e30f;
    float l0v = 0.f, l1v = 0.f;

    const int nkt  = 2 * qt + 2;
    const int r_hi = q0 + wq * 16 + 15;

    for (int kt = 0; kt < nkt; kt++) {
        const int k0 = kt * 64;
        const uint32_t s  = (uint32_t)(kt & 1);
        const uint32_t cp = (uint32_t)((kt >> 1) & 1);

        if (kt >= 1 && kt + 1 < nkt) {
            const uint32_t so = s ^ 1u;
            mbar_wait(mbE + so * 8, (uint32_t)(((kt - 1) >> 1) & 1));
            attn_issue_kv(kp, vp, (kt + 1) * 64,
                          sKs + so * KVBUFB, sVs + so * KVBUFB, tid);
            CPA_MBAR_ARRIVE(mbF + so * 8);
        }

        mbar_wait(mbF + s * 8, cp);

        if (kt == 0) {
#pragma unroll
            for (int ks = 0; ks < 4; ks++)
                LDM_X4(qf[ks], q_lm + ks * 32);
        }

        if (k0 <= r_hi) {
            const uint32_t Kb = sKs + s * KVBUFB;
            const uint32_t Vb = sVs + s * KVBUFB;

            // ---- S = Q @ K^T ----
            float sacc[8][4];
#pragma unroll
            for (int nt = 0; nt < 8; nt++)
#pragma unroll
                for (int q = 0; q < 4; q++) sacc[nt][q] = 0.f;

#pragma unroll
            for (int ks = 0; ks < 4; ks++) {
#pragma unroll
                for (int nt2 = 0; nt2 < 4; nt2++) {
                    uint32_t bf[4];
                    LDM_X4(bf, Kb + kv_lm + nt2 * 2304 + ks * 32);
                    MMA_F16(sacc[2 * nt2],     qf[ks], &bf[0]);
                    MMA_F16(sacc[2 * nt2 + 1], qf[ks], &bf[2]);
                }
            }

            // ---- causal mask ----
            if (kt >= 2 * qt) {
                int r0g = q0 + wq * 16 + lr;
#pragma unroll
                for (int nt = 0; nt < 8; nt++) {
                    int c0g = k0 + nt * 8 + 2 * lc;
                    if (c0g     > r0g)     sacc[nt][0] = -1e30f;
                    if (c0g + 1 > r0g)     sacc[nt][1] = -1e30f;
                    if (c0g     > r0g + 8) sacc[nt][2] = -1e30f;
                    if (c0g + 1 > r0g + 8) sacc[nt][3] = -1e30f;
                }
            }

            // ---- online softmax (exp2) ----
            float rm0 = -1e30f, rm1 = -1e30f;
#pragma unroll
            for (int nt = 0; nt < 8; nt++) {
                rm0 = fmaxf(rm0, fmaxf(sacc[nt][0], sacc[nt][1]));
                rm1 = fmaxf(rm1, fmaxf(sacc[nt][2], sacc[nt][3]));
            }
            rm0 = fmaxf(rm0, __shfl_xor_sync(0xffffffffu, rm0, 1));
            rm0 = fmaxf(rm0, __shfl_xor_sync(0xffffffffu, rm0, 2));
            rm1 = fmaxf(rm1, __shfl_xor_sync(0xffffffffu, rm1, 1));
            rm1 = fmaxf(rm1, __shfl_xor_sync(0xffffffffu, rm1, 2));

            float mn0 = fmaxf(m0v, rm0);
            float mn1 = fmaxf(m1v, rm1);
            float cr0 = exp2f(m0v - mn0);
            float cr1 = exp2f(m1v - mn1);
            m0v = mn0; m1v = mn1;

            float rs0 = 0.f, rs1 = 0.f;
#pragma unroll
            for (int nt = 0; nt < 8; nt++) {
                sacc[nt][0] = exp2f(sacc[nt][0] - mn0);
                sacc[nt][1] = exp2f(sacc[nt][1] - mn0);
                sacc[nt][2] = exp2f(sacc[nt][2] - mn1);
                sacc[nt][3] = exp2f(sacc[nt][3] - mn1);
                rs0 += sacc[nt][0] + sacc[nt][1];
                rs1 += sacc[nt][2] + sacc[nt][3];
            }
            rs0 += __shfl_xor_sync(0xffffffffu, rs0, 1);
            rs0 += __shfl_xor_sync(0xffffffffu, rs0, 2);
            rs1 += __shfl_xor_sync(0xffffffffu, rs1, 1);
            rs1 += __shfl_xor_sync(0xffffffffu, rs1, 2);
            l0v = l0v * cr0 + rs0;
            l1v = l1v * cr1 + rs1;
#pragma unroll
            for (int nt = 0; nt < 8; nt++) {
                o[nt][0] *= cr0; o[nt][1] *= cr0;
                o[nt][2] *= cr1; o[nt][3] *= cr1;
            }

            // ---- O += P @ V : P A-fragments repacked in registers ----
            // m16n8k16 A-frag = two consecutive m16n8 accumulator frags:
            // a0 = (lr, 2lc..)=sacc[2ks][0..1], a1 = (lr+8,..)=sacc[2ks][2..3],
            // a2/a3 = same for sacc[2ks+1] (k = kv cols 16ks+8..15).
#pragma unroll
            for (int ks = 0; ks < 4; ks++) {
                uint32_t a[4];
                a[0] = packh2(sacc[2 * ks][0],     sacc[2 * ks][1]);
                a[1] = packh2(sacc[2 * ks][2],     sacc[2 * ks][3]);
                a[2] = packh2(sacc[2 * ks + 1][0], sacc[2 * ks + 1][1]);
                a[3] = packh2(sacc[2 * ks + 1][2], sacc[2 * ks + 1][3]);
#pragma unroll
                for (int nt2 = 0; nt2 < 4; nt2++) {
                    uint32_t b[4];
                    LDM_X4(b, Vb + kv_lm + nt2 * 2304 + ks * 32);
                    MMA_F16(o[2 * nt2],     a, &b[0]);
                    MMA_F16(o[2 * nt2 + 1], a, &b[2]);
                }
            }
        }

        __syncwarp();
        if (lane == 0) MBAR_ARRIVE(mbE + s * 8);
    }

    // ---- normalize + store to [b,t,c] (fp16: feeds proj) ----
    const int b = bh >> 4, h = bh & 15;
    const int r0g = q0 + wq * 16 + lr;
    const float inv0 = 1.0f / l0v;
    const float inv1 = 1.0f / l1v;
#pragma unroll
    for (int nt = 0; nt < 8; nt++) {
        int cg = h * 64 + nt * 8 + 2 * lc;
        *reinterpret_cast<__half2*>(
            &g_att16[(size_t)(b * SEQ + r0g) * CH + cg]) =
            __floats2half2_rn(o[nt][0] * inv0, o[nt][1] * inv0);
        *reinterpret_cast<__half2*>(
            &g_att16[(size_t)(b * SEQ + r0g + 8) * CH + cg]) =
            __floats2half2_rn(o[nt][2] * inv1, o[nt][3] * inv1);
    }
}

// ---------------------------------------------------------------------------
extern "C" void kernel_launch(void* const* d_in, const int* in_sizes, int n_in,
                              void* d_out, int out_size)
{
    const float* x      = (const float*)d_in[0];
    const float* w_attn = (const float*)d_in[1];
    const float* b_attn = (const float*)d_in[2];
    const float* w_proj = (const float*)d_in[3];
    const float* b_proj = (const float*)d_in[4];
    float* out = (float*)d_out;

    cudaFuncSetAttribute(qkv_gemm_kernel,
                         cudaFuncAttributeMaxDynamicSharedMemorySize, GEMM_SMEM);
    cudaFuncSetAttribute(proj_gemm_kernel,
                         cudaFuncAttributeMaxDynamicSharedMemorySize, GEMM_SMEM);
    cudaFuncSetAttribute(attn_kernel,
                         cudaFuncAttributeMaxDynamicSharedMemorySize, ATTN_SMEM);

    // 0) fp16-convert x; transpose+convert weights to [N][K]
    cvt_x_kernel<<<(BATCH * SEQ * CH / 4 + 255) / 256, 256>>>(x,
        BATCH * SEQ * CH / 4);
    cvt_T_kernel<<<dim3(3 * CH / 32, CH / 32), dim3(32, 8)>>>(w_attn, 1, 3 * CH);
    cvt_T_kernel<<<dim3(CH / 32, CH / 32), dim3(32, 8)>>>(w_proj, 2, CH);

    // 1) QKV GEMM: grid (3072/128, 8192/128)
    qkv_gemm_kernel<<<dim3(24, 64), 256, GEMM_SMEM>>>(b_attn);

    // 2) Attention: grid (16 q-tiles, B*NH)
    attn_kernel<<<dim3(16, BATCH * NHEAD), 256, ATTN_SMEM>>>();

    // 3) Projection: grid (1024/128, 8192/128)
    proj_gemm_kernel<<<dim3(8, 64), 256, GEMM_SMEM>>>(b_proj, out);
}

// round 15
// speedup vs baseline: 2.1047x; 1.0434x over previous
#include <cuda_runtime.h>
#include <cuda_fp16.h>
#include <cstdint>

#define BATCH 4
#define SEQ   2048
#define CH    1024
#define NHEAD 16
#define HDIM  64
#define LOG2E 1.4426950408889634f

// Scratch (allocation-free rule: __device__ globals). All operands fp16.
// q,k: [b,h,t,d]; v: [b,h,d,t] (transposed for PV ldmatrix).
__device__ __half g_q16[BATCH * NHEAD * SEQ * HDIM];
__device__ __half g_k16[BATCH * NHEAD * SEQ * HDIM];
__device__ __half g_v16[BATCH * NHEAD * HDIM * SEQ];
__device__ __half g_att16[BATCH * SEQ * CH];     // [b,t,c]
__device__ __half g_x16 [BATCH * SEQ * CH];      // x
__device__ __half g_wa16[3 * CH * CH];           // w_attn^T: [3072][1024]
__device__ __half g_wp16[CH * CH];               // w_proj^T: [1024][1024]

#define MMA_F16(d, a, b)                                                   \
    asm volatile(                                                          \
        "mma.sync.aligned.m16n8k16.row.col.f32.f16.f16.f32 "               \
        "{%0,%1,%2,%3},{%4,%5,%6,%7},{%8,%9},{%0,%1,%2,%3};"               \
        : "+f"((d)[0]), "+f"((d)[1]), "+f"((d)[2]), "+f"((d)[3])           \
        : "r"((a)[0]), "r"((a)[1]), "r"((a)[2]), "r"((a)[3]),              \
          "r"((b)[0]), "r"((b)[1]))

#define LDM_X4(r, addr)                                                    \
    asm volatile("ldmatrix.sync.aligned.m8n8.x4.shared.b16 "               \
                 "{%0,%1,%2,%3}, [%4];"                                    \
                 : "=r"((r)[0]), "=r"((r)[1]), "=r"((r)[2]), "=r"((r)[3])  \
                 : "r"(addr))

#define CP_ASYNC16(dst_u32, src_ptr)                                       \
    asm volatile("cp.async.cg.shared.global [%0], [%1], 16;"               \
                 :: "r"(dst_u32), "l"(src_ptr))
#define CP_COMMIT() asm volatile("cp.async.commit_group;")
#define CP_WAIT(N)  asm volatile("cp.async.wait_group %0;" :: "n"(N))

#define MBAR_INIT(addr, cnt)                                               \
    asm volatile("mbarrier.init.shared::cta.b64 [%0], %1;"                 \
                 :: "r"(addr), "r"((uint32_t)(cnt)) : "memory")
#define MBAR_ARRIVE(addr)                                                  \
    asm volatile("{\n\t.reg .b64 t;\n\t"                                   \
                 "mbarrier.arrive.shared::cta.b64 t, [%0];\n\t}"           \
                 :: "r"(addr) : "memory")
#define CPA_MBAR_ARRIVE(addr)                                              \
    asm volatile("cp.async.mbarrier.arrive.noinc.shared::cta.b64 [%0];"    \
                 :: "r"(addr) : "memory")

__device__ __forceinline__ void mbar_wait(uint32_t mbar, uint32_t parity) {
    asm volatile(
        "{\n\t.reg .pred P;\n\t"
        "W_%=:\n\t"
        "mbarrier.try_wait.parity.acquire.cta.shared::cta.b64 P, [%0], %1, 0x989680;\n\t"
        "@!P bra W_%=;\n\t"
        "}" :: "r"(mbar), "r"(parity) : "memory");
}

__device__ __forceinline__ uint32_t smem_u32(const void* p) {
    return (uint32_t)__cvta_generic_to_shared(p);
}

__device__ __forceinline__ uint32_t packh2(float a, float b) {
    __half2 h = __floats2half2_rn(a, b);
    return *reinterpret_cast<uint32_t*>(&h);
}

// two fp16 exp2 in one MUFU op
__device__ __forceinline__ uint32_t ex2h2(uint32_t x) {
    uint32_t r;
    asm("ex2.approx.f16x2 %0, %1;" : "=r"(r) : "r"(x));
    return r;
}

// ---------------------------------------------------------------------------
// Prologue converts (fp32 -> fp16)
// ---------------------------------------------------------------------------
__global__ void cvt_x_kernel(const float* __restrict__ src, int n4)
{
    int i = blockIdx.x * blockDim.x + threadIdx.x;
    if (i < n4) {
        float4 v = reinterpret_cast<const float4*>(src)[i];
        __half2 h0 = __floats2half2_rn(v.x, v.y);
        __half2 h1 = __floats2half2_rn(v.z, v.w);
        reinterpret_cast<__half2*>(g_x16)[2 * i]     = h0;
        reinterpret_cast<__half2*>(g_x16)[2 * i + 1] = h1;
    }
}

// Transpose + fp16: src [CH][N] -> dst [N][CH]
__global__ void cvt_T_kernel(const float* __restrict__ src, int sel, int N)
{
    __shared__ float tile[32][33];
    __half* dst = (sel == 1) ? g_wa16 : g_wp16;
    int n0 = blockIdx.x * 32, k0 = blockIdx.y * 32;
    int tx = threadIdx.x, ty = threadIdx.y;  // 32 x 8
#pragma unroll
    for (int i = 0; i < 4; i++)
        tile[ty + 8 * i][tx] = src[(size_t)(k0 + ty + 8 * i) * N + n0 + tx];
    __syncthreads();
#pragma unroll
    for (int i = 0; i < 2; i++) {
        int nl = ty + i * 8 + (tx >> 4) * 16;
        int kc = (tx & 15) * 2;
        __half2 h = __floats2half2_rn(tile[kc][nl], tile[kc + 1][nl]);
        *reinterpret_cast<__half2*>(dst + (size_t)(n0 + nl) * CH + k0 + kc) = h;
    }
}

// ---------------------------------------------------------------------------
// FP16 GEMM core (round-13 proven): block 128x128, BK=64, 8 warps (2x4),
// 3-stage mbarrier producer/consumer ring + register double-buffered A frags.
// ---------------------------------------------------------------------------
#define GP 72
#define GROWB (GP * 2)
#define GBUFB (128 * GROWB)
#define NSTAGE 3
#define GEMM_SMEM (2 * NSTAGE * GBUFB + 64)

__device__ __forceinline__ void gemm_issue_loads(
    const __half* __restrict__ A, const __half* __restrict__ B,
    int m0, int n0, int k0, uint32_t sA, uint32_t sB, int tid)
{
#pragma unroll
    for (int it = 0; it < 4; it++) {
        int idx = it * 256 + tid;
        int row = idx >> 3, c = idx & 7;
        CP_ASYNC16(sA + row * GROWB + c * 16,
                   A + (size_t)(m0 + row) * CH + k0 + c * 8);
    }
#pragma unroll
    for (int it = 0; it < 4; it++) {
        int idx = it * 256 + tid;
        int row = idx >> 3, c = idx & 7;
        CP_ASYNC16(sB + row * GROWB + c * 16,
                   B + (size_t)(n0 + row) * CH + k0 + c * 8);
    }
}

__device__ __forceinline__ void f16_gemm_tile(
    const __half* __restrict__ A, const __half* __restrict__ B,
    int m0, int n0,
    float acc[4][4][4],
    uint32_t sbase, int tid)
{
    const int lane  = tid & 31;
    const int wid   = tid >> 5;
    const int wm    = wid & 1;
    const int wn    = wid >> 1;
    const int l16   = lane & 15;
    const int lane8 = lane & 7;

    const uint32_t sA0 = sbase;
    const uint32_t sB0 = sbase + NSTAGE * GBUFB;
    const uint32_t mbF = sbase + 2 * NSTAGE * GBUFB;
    const uint32_t mbE = mbF + 24;

    const uint32_t a_lm =
        ((wm * 64 + l16) * GP + (lane >> 4) * 8) * 2;
    const uint32_t b_lm =
        ((wn * 32 + (lane >> 4) * 8 + lane8) * GP +
         ((lane >> 3) & 1) * 8) * 2;

    if (tid == 0) {
#pragma unroll
        for (int i = 0; i < NSTAGE; i++) {
            MBAR_INIT(mbF + i * 8, 256);
            MBAR_INIT(mbE + i * 8, 8);
        }
    }
    __syncthreads();

    gemm_issue_loads(A, B, m0, n0, 0, sA0, sB0, tid);
    CPA_MBAR_ARRIVE(mbF + 0);
    gemm_issue_loads(A, B, m0, n0, 64, sA0 + GBUFB, sB0 + GBUFB, tid);
    CPA_MBAR_ARRIVE(mbF + 8);

    const int nk = CH / 64;   // 16
    int s = 0;  uint32_t fp = 0;
    int s2 = 2;
    int cc = 0; uint32_t ep = 0;

    for (int ki = 0; ki < nk; ki++) {
        mbar_wait(mbF + s * 8, fp);

        const uint32_t Ab = sA0 + s * GBUFB;
        const uint32_t Bb = sB0 + s * GBUFB;

        uint32_t af[2][4][4];
#pragma unroll
        for (int mt = 0; mt < 4; mt++)
            LDM_X4(af[0][mt], Ab + a_lm + mt * 2304);

#pragma unroll
        for (int ks = 0; ks < 4; ks++) {
            const int cur = ks & 1;
            uint32_t bf[2][4];
            LDM_X4(bf[0], Bb + b_lm + ks * 32);
            LDM_X4(bf[1], Bb + b_lm + 2304 + ks * 32);
            if (ks < 3) {
#pragma unroll
                for (int mt = 0; mt < 4; mt++)
                    LDM_X4(af[cur ^ 1][mt],
                           Ab + a_lm + mt * 2304 + (ks + 1) * 32);
            }
#pragma unroll
            for (int mt = 0; mt < 4; mt++) {
#pragma unroll
                for (int nt2 = 0; nt2 < 2; nt2++) {
                    MMA_F16(acc[mt][2 * nt2],     af[cur][mt], &bf[nt2][0]);
                    MMA_F16(acc[mt][2 * nt2 + 1], af[cur][mt], &bf[nt2][2]);
                }
            }
        }

        if (ki + 2 < nk) {
            if (ki >= 1) {
                mbar_wait(mbE + s2 * 8, ep);
                cc++; if (cc == 3) { cc = 0; ep ^= 1; }
            }
            gemm_issue_loads(A, B, m0, n0, (ki + 2) * 64,
                             sA0 + s2 * GBUFB, sB0 + s2 * GBUFB, tid);
            CPA_MBAR_ARRIVE(mbF + s2 * 8);
        }

        __syncwarp();
        if (lane == 0) MBAR_ARRIVE(mbE + s * 8);

        s = (s + 1 == NSTAGE) ? 0 : s + 1;
        if (s == 0) fp ^= 1;
        s2 = (s2 + 1 == NSTAGE) ? 0 : s2 + 1;
    }
}

// ---------------------------------------------------------------------------
// Kernel 1: QKV GEMM (round-13 proven epilogues).
// ---------------------------------------------------------------------------
#define VPS 144

__global__ __launch_bounds__(256, 2) void qkv_gemm_kernel(
    const float* __restrict__ bias)
{
    extern __shared__ float smg[];
    const uint32_t sbase = smem_u32(smg);
    const int tid = threadIdx.x;
    const int m0 = blockIdx.y * 128;
    const int n0 = blockIdx.x * 128;

    float acc[4][4][4];
#pragma unroll
    for (int i = 0; i < 4; i++)
#pragma unroll
        for (int j = 0; j < 4; j++)
#pragma unroll
            for (int q = 0; q < 4; q++) acc[i][j][q] = 0.f;

    f16_gemm_tile(g_x16, g_wa16, m0, n0, acc, sbase, tid);
    __syncthreads();

    const int lane = tid & 31;
    const int wid  = tid >> 5;
    const int wm   = wid & 1;
    const int wn   = wid >> 1;
    const int lr   = lane >> 2;
    const int lc   = lane & 3;

    const int sec = n0 >> 10;
    const float scale = (sec == 0) ? 0.125f * LOG2E : 1.0f;
    const int bb = m0 >> 11;
    const int t0 = m0 & (SEQ - 1);

    if (sec < 2) {
        __half* dst = (sec == 0) ? g_q16 : g_k16;
#pragma unroll
        for (int mt = 0; mt < 4; mt++) {
            int t = t0 + wm * 64 + mt * 16 + lr;
#pragma unroll
            for (int nt = 0; nt < 4; nt++) {
                int c0 = n0 + wn * 32 + nt * 8 + lc * 2;
                float b0 = bias[c0], b1 = bias[c0 + 1];
                int n1 = c0 & (CH - 1);
                int h  = n1 >> 6;
                int d  = n1 & 63;
                __half* p = dst + ((size_t)((bb * NHEAD + h) * SEQ + t)) * HDIM + d;
                *reinterpret_cast<__half2*>(p) =
                    __floats2half2_rn((acc[mt][nt][0] + b0) * scale,
                                      (acc[mt][nt][1] + b1) * scale);
                *reinterpret_cast<__half2*>(p + 8 * HDIM) =
                    __floats2half2_rn((acc[mt][nt][2] + b0) * scale,
                                      (acc[mt][nt][3] + b1) * scale);
            }
        }
    } else {
        __half* smh = reinterpret_cast<__half*>(smg);
#pragma unroll
        for (int mt = 0; mt < 4; mt++) {
            int rm = wm * 64 + mt * 16 + lr;
#pragma unroll
            for (int nt = 0; nt < 4; nt++) {
                int cc = wn * 32 + nt * 8 + lc * 2;
                float b0 = bias[n0 + cc], b1 = bias[n0 + cc + 1];
                smh[cc * VPS + rm]           = __float2half_rn(acc[mt][nt][0] + b0);
                smh[(cc + 1) * VPS + rm]     = __float2half_rn(acc[mt][nt][1] + b1);
                smh[cc * VPS + rm + 8]       = __float2half_rn(acc[mt][nt][2] + b0);
                smh[(cc + 1) * VPS + rm + 8] = __float2half_rn(acc[mt][nt][3] + b1);
            }
        }
        __syncthreads();
        const int l16 = lane & 15;
#pragma unroll
        for (int it = 0; it < 8; it++) {
            int c = wid * 16 + it * 2 + (lane >> 4);
            uint4 val = *reinterpret_cast<uint4*>(&smh[c * VPS + l16 * 8]);
            int n1 = (n0 + c) & (CH - 1);
            int h = n1 >> 6, d = n1 & 63;
            __half* p = g_v16 +
                ((size_t)((bb * NHEAD + h) * HDIM + d)) * SEQ + t0 + l16 * 8;
            *reinterpret_cast<uint4*>(p) = val;
        }
    }
}

// ---------------------------------------------------------------------------
// Kernel 3: output projection
// ---------------------------------------------------------------------------
__global__ __launch_bounds__(256, 2) void proj_gemm_kernel(
    const float* __restrict__ bias, float* __restrict__ out)
{
    extern __shared__ float smg[];
    const uint32_t sbase = smem_u32(smg);
    const int tid = threadIdx.x;
    const int m0 = blockIdx.y * 128;
    const int n0 = blockIdx.x * 128;

    float acc[4][4][4];
#pragma unroll
    for (int i = 0; i < 4; i++)
#pragma unroll
        for (int j = 0; j < 4; j++)
#pragma unroll
            for (int q = 0; q < 4; q++) acc[i][j][q] = 0.f;

    f16_gemm_tile(g_att16, g_wp16, m0, n0, acc, sbase, tid);

    const int lane = tid & 31;
    const int wid  = tid >> 5;
    const int wm   = wid & 1;
    const int wn   = wid >> 1;
    const int lr   = lane >> 2;
    const int lc   = lane & 3;

#pragma unroll
    for (int mt = 0; mt < 4; mt++) {
        int r0 = m0 + wm * 64 + mt * 16 + lr;
#pragma unroll
        for (int nt = 0; nt < 4; nt++) {
            int c0 = n0 + wn * 32 + nt * 8 + lc * 2;
            float b0 = bias[c0], b1 = bias[c0 + 1];
            *reinterpret_cast<float2*>(&out[(size_t)r0 * CH + c0]) =
                make_float2(acc[mt][nt][0] + b0, acc[mt][nt][1] + b1);
            *reinterpret_cast<float2*>(&out[(size_t)(r0 + 8) * CH + c0]) =
                make_float2(acc[mt][nt][2] + b0, acc[mt][nt][3] + b1);
        }
    }
}

// ---------------------------------------------------------------------------
// Kernel 2: causal flash attention, fp16 mma m16n8k16, mbarrier pipeline.
// NEW: P via ex2.approx.f16x2 (halved MUFU, fused with the fp16 pack) and
// row sums via ones-MMA on the tensor pipe (no FFMA chain / sum shuffles).
// ---------------------------------------------------------------------------
#define AP 72
#define AROWB (AP * 2)
#define QBUFB (128 * AROWB)
#define KVBUFB (64 * AROWB)
#define ATTN_SMEM (QBUFB + 4 * KVBUFB + 32)

__device__ __forceinline__ void attn_issue_kv(
    const __half* __restrict__ kp, const __half* __restrict__ vp,
    int k0, uint32_t sK, uint32_t sV, int tid)
{
#pragma unroll
    for (int it = 0; it < 2; it++) {
        int idx = it * 256 + tid;
        int row = idx >> 3;
        int c   = idx & 7;
        CP_ASYNC16(sK + row * AROWB + c * 16,
                   kp + (size_t)(k0 + row) * HDIM + c * 8);
        CP_ASYNC16(sV + row * AROWB + c * 16,
                   vp + (size_t)row * SEQ + k0 + c * 8);
    }
}

__global__ __launch_bounds__(256, 2) void attn_kernel()
{
    extern __shared__ float sm[];
    const uint32_t sbase = smem_u32(sm);
    const uint32_t sQs = sbase;
    const uint32_t sKs = sbase + QBUFB;
    const uint32_t sVs = sKs + 2 * KVBUFB;
    const uint32_t mbF = sVs + 2 * KVBUFB;
    const uint32_t mbE = mbF + 16;

    const int tid   = threadIdx.x;
    const int lane  = tid & 31;
    const int wq    = tid >> 5;
    const int lr    = lane >> 2;
    const int lc    = lane & 3;
    const int l16   = lane & 15;
    const int lane8 = lane & 7;

    const int qt = (int)gridDim.x - 1 - (int)blockIdx.x;  // big tiles first
    const int bh = blockIdx.y;
    const int q0 = qt * 128;

    const __half* qp = g_q16 + (size_t)bh * SEQ * HDIM;
    const __half* kp = g_k16 + (size_t)bh * SEQ * HDIM;
    const __half* vp = g_v16 + (size_t)bh * HDIM * SEQ;

    const uint32_t q_lm = sQs +
        ((wq * 16 + l16) * AP + (lane >> 4) * 8) * 2;
    const uint32_t kv_lm =
        (((lane >> 4) * 8 + lane8) * AP + ((lane >> 3) & 1) * 8) * 2;

    if (tid == 0) {
        MBAR_INIT(mbF + 0, 256);
        MBAR_INIT(mbF + 8, 256);
        MBAR_INIT(mbE + 0, 8);
        MBAR_INIT(mbE + 8, 8);
    }
    __syncthreads();

#pragma unroll
    for (int it = 0; it < 4; it++) {
        int idx = it * 256 + tid;
        int row = idx >> 3;
        int c   = idx & 7;
        CP_ASYNC16(sQs + row * AROWB + c * 16,
                   qp + (size_t)(q0 + row) * HDIM + c * 8);
    }
    attn_issue_kv(kp, vp, 0, sKs, sVs, tid);
    CPA_MBAR_ARRIVE(mbF + 0);
    attn_issue_kv(kp, vp, 64, sKs + KVBUFB, sVs + KVBUFB, tid);
    CPA_MBAR_ARRIVE(mbF + 8);

    uint32_t qf[4][4];

    float o[8][4] = {};
    float m0v = -1e30f, m1v = -1e30f;
    float l0v = 0.f, l1v = 0.f;

    const uint32_t ONES2 = 0x3C003C00u;   // half2(1.0, 1.0)
    uint32_t b_ones[2] = {ONES2, ONES2};

    const int nkt  = 2 * qt + 2;
    const int r_hi = q0 + wq * 16 + 15;

    for (int kt = 0; kt < nkt; kt++) {
        const int k0 = kt * 64;
        const uint32_t s  = (uint32_t)(kt & 1);
        const uint32_t cp = (uint32_t)((kt >> 1) & 1);

        if (kt >= 1 && kt + 1 < nkt) {
            const uint32_t so = s ^ 1u;
            mbar_wait(mbE + so * 8, (uint32_t)(((kt - 1) >> 1) & 1));
            attn_issue_kv(kp, vp, (kt + 1) * 64,
                          sKs + so * KVBUFB, sVs + so * KVBUFB, tid);
            CPA_MBAR_ARRIVE(mbF + so * 8);
        }

        mbar_wait(mbF + s * 8, cp);

        if (kt == 0) {
#pragma unroll
            for (int ks = 0; ks < 4; ks++)
                LDM_X4(qf[ks], q_lm + ks * 32);
        }

        if (k0 <= r_hi) {
            const uint32_t Kb = sKs + s * KVBUFB;
            const uint32_t Vb = sVs + s * KVBUFB;

            // ---- S = Q @ K^T ----
            float sacc[8][4];
#pragma unroll
            for (int nt = 0; nt < 8; nt++)
#pragma unroll
                for (int q = 0; q < 4; q++) sacc[nt][q] = 0.f;

#pragma unroll
            for (int ks = 0; ks < 4; ks++) {
#pragma unroll
                for (int nt2 = 0; nt2 < 4; nt2++) {
                    uint32_t bf[4];
                    LDM_X4(bf, Kb + kv_lm + nt2 * 2304 + ks * 32);
                    MMA_F16(sacc[2 * nt2],     qf[ks], &bf[0]);
                    MMA_F16(sacc[2 * nt2 + 1], qf[ks], &bf[2]);
                }
            }

            // ---- causal mask ----
            if (kt >= 2 * qt) {
                int r0g = q0 + wq * 16 + lr;
#pragma unroll
                for (int nt = 0; nt < 8; nt++) {
                    int c0g = k0 + nt * 8 + 2 * lc;
                    if (c0g     > r0g)     sacc[nt][0] = -1e30f;
                    if (c0g + 1 > r0g)     sacc[nt][1] = -1e30f;
                    if (c0g     > r0g + 8) sacc[nt][2] = -1e30f;
                    if (c0g + 1 > r0g + 8) sacc[nt][3] = -1e30f;
                }
            }

            // ---- online softmax: max reduce (fp32), P via f16x2 ex2 ----
            float rm0 = -1e30f, rm1 = -1e30f;
#pragma unroll
            for (int nt = 0; nt < 8; nt++) {
                rm0 = fmaxf(rm0, fmaxf(sacc[nt][0], sacc[nt][1]));
                rm1 = fmaxf(rm1, fmaxf(sacc[nt][2], sacc[nt][3]));
            }
            rm0 = fmaxf(rm0, __shfl_xor_sync(0xffffffffu, rm0, 1));
            rm0 = fmaxf(rm0, __shfl_xor_sync(0xffffffffu, rm0, 2));
            rm1 = fmaxf(rm1, __shfl_xor_sync(0xffffffffu, rm1, 1));
            rm1 = fmaxf(rm1, __shfl_xor_sync(0xffffffffu, rm1, 2));

            float mn0 = fmaxf(m0v, rm0);
            float mn1 = fmaxf(m1v, rm1);
            float cr0 = exp2f(m0v - mn0);
            float cr1 = exp2f(m1v - mn1);
            m0v = mn0; m1v = mn1;

            // P fragments: pf[nt][0] rows lr, pf[nt][1] rows lr+8 (fp16x2)
            uint32_t pf[8][2];
#pragma unroll
            for (int nt = 0; nt < 8; nt++) {
                pf[nt][0] = ex2h2(packh2(sacc[nt][0] - mn0, sacc[nt][1] - mn0));
                pf[nt][1] = ex2h2(packh2(sacc[nt][2] - mn1, sacc[nt][3] - mn1));
            }

#pragma unroll
            for (int nt = 0; nt < 8; nt++) {
                o[nt][0] *= cr0; o[nt][1] *= cr0;
                o[nt][2] *= cr1; o[nt][3] *= cr1;
            }

            // ---- O += P @ V and row sums via ones-MMA ----
            float dsum[4] = {0.f, 0.f, 0.f, 0.f};
#pragma unroll
            for (int ks = 0; ks < 4; ks++) {
                uint32_t a[4];
                a[0] = pf[2 * ks][0];
                a[1] = pf[2 * ks][1];
                a[2] = pf[2 * ks + 1][0];
                a[3] = pf[2 * ks + 1][1];
                MMA_F16(dsum, a, b_ones);
#pragma unroll
                for (int nt2 = 0; nt2 < 4; nt2++) {
                    uint32_t b[4];
                    LDM_X4(b, Vb + kv_lm + nt2 * 2304 + ks * 32);
                    MMA_F16(o[2 * nt2],     a, &b[0]);
                    MMA_F16(o[2 * nt2 + 1], a, &b[2]);
                }
            }
            l0v = l0v * cr0 + dsum[0];   // rowsum(lr)
            l1v = l1v * cr1 + dsum[2];   // rowsum(lr+8)
        }

        __syncwarp();
        if (lane == 0) MBAR_ARRIVE(mbE + s * 8);
    }

    // ---- normalize + store to [b,t,c] (fp16: feeds proj) ----
    const int b = bh >> 4, h = bh & 15;
    const int r0g = q0 + wq * 16 + lr;
    const float inv0 = 1.0f / l0v;
    const float inv1 = 1.0f / l1v;
#pragma unroll
    for (int nt = 0; nt < 8; nt++) {
        int cg = h * 64 + nt * 8 + 2 * lc;
        *reinterpret_cast<__half2*>(
            &g_att16[(size_t)(b * SEQ + r0g) * CH + cg]) =
            __floats2half2_rn(o[nt][0] * inv0, o[nt][1] * inv0);
        *reinterpret_cast<__half2*>(
            &g_att16[(size_t)(b * SEQ + r0g + 8) * CH + cg]) =
            __floats2half2_rn(o[nt][2] * inv1, o[nt][3] * inv1);
    }
}

// ---------------------------------------------------------------------------
extern "C" void kernel_launch(void* const* d_in, const int* in_sizes, int n_in,
                              void* d_out, int out_size)
{
    const float* x      = (const float*)d_in[0];
    const float* w_attn = (const float*)d_in[1];
    const float* b_attn = (const float*)d_in[2];
    const float* w_proj = (const float*)d_in[3];
    const float* b_proj = (const float*)d_in[4];
    float* out = (float*)d_out;

    cudaFuncSetAttribute(qkv_gemm_kernel,
                         cudaFuncAttributeMaxDynamicSharedMemorySize, GEMM_SMEM);
    cudaFuncSetAttribute(proj_gemm_kernel,
                         cudaFuncAttributeMaxDynamicSharedMemorySize, GEMM_SMEM);
    cudaFuncSetAttribute(attn_kernel,
                         cudaFuncAttributeMaxDynamicSharedMemorySize, ATTN_SMEM);

    // 0) fp16-convert x; transpose+convert weights to [N][K]
    cvt_x_kernel<<<(BATCH * SEQ * CH / 4 + 255) / 256, 256>>>(x,
        BATCH * SEQ * CH / 4);
    cvt_T_kernel<<<dim3(3 * CH / 32, CH / 32), dim3(32, 8)>>>(w_attn, 1, 3 * CH);
    cvt_T_kernel<<<dim3(CH / 32, CH / 32), dim3(32, 8)>>>(w_proj, 2, CH);

    // 1) QKV GEMM: grid (3072/128, 8192/128)
    qkv_gemm_kernel<<<dim3(24, 64), 256, GEMM_SMEM>>>(b_attn);

    // 2) Attention: grid (16 q-tiles, B*NH)
    attn_kernel<<<dim3(16, BATCH * NHEAD), 256, ATTN_SMEM>>>();

    // 3) Projection: grid (1024/128, 8192/128)
    proj_gemm_kernel<<<dim3(8, 64), 256, GEMM_SMEM>>>(b_proj, out);
}